// round 1
// baseline (speedup 1.0000x reference)
#include <cuda_runtime.h>
#include <cuda_bf16.h>
#include <math.h>

// Problem dims
#define B_   128
#define S_   196
#define K_   512
#define TCAP 16
#define TOUT 15
#define V_   32000
#define E_   512
#define H_   512

// ---------------- scratch (device globals; allocation-free) ----------------
__device__ float g_keys[(size_t)B_ * S_ * H_];     // keys_proj (B,S,H)   51.4 MB
__device__ float g_xe[TOUT * B_ * E_];             // gathered embeddings (t*128+b, E)
__device__ float g_x[TOUT * B_ * H_];              // fc1 output          (t*128+b, H)
__device__ float g_gix[TOUT * B_ * 3 * H_];        // x_t @ Wx^T          (t*128+b, 1536)
__device__ float g_h[(TOUT + 1) * B_ * H_];        // h_0..h_15           (t, b, H)
__device__ float g_q[B_ * H_];
__device__ float g_ctx[B_ * K_];
__device__ float g_ctxh[B_ * H_];
__device__ float g_gi[B_ * 3 * H_];
__device__ float g_gh[B_ * 3 * H_];

// ---------------- big NT SGEMM: C[M,N] = A[M,K] * B[N,K]^T -----------------
// BM=BN=128, BK=8, 256 threads, 8x8 microtile. M%128==0, N%128==0, K%8==0.
// mode: 0 plain, 1 +bias, 2 +bias+Add, 3 +bias, remap row m=(t*128+b) -> C[(b*15+t)*ldc+n]
__global__ __launch_bounds__(256) void sgemm_nt_big(
    const float* __restrict__ A, int lda,
    const float* __restrict__ B, int ldb,
    float* __restrict__ C, int ldc, int K,
    const float* __restrict__ bias,
    const float* __restrict__ Add, int ldadd, int mode)
{
    __shared__ float As[8][128];
    __shared__ float Bs[8][128];
    int tid = threadIdx.x;
    int bn = blockIdx.x, bm = blockIdx.y;
    int ldrow = tid >> 1;
    int ldk   = (tid & 1) * 4;
    const float* Ap = A + (size_t)(bm * 128 + ldrow) * lda + ldk;
    const float* Bp = B + (size_t)(bn * 128 + ldrow) * ldb + ldk;
    int tx = tid & 15, ty = tid >> 4;
    float acc[8][8] = {};

    for (int k0 = 0; k0 < K; k0 += 8) {
        float4 a4 = *(const float4*)(Ap + k0);
        float4 b4 = *(const float4*)(Bp + k0);
        As[ldk + 0][ldrow] = a4.x; As[ldk + 1][ldrow] = a4.y;
        As[ldk + 2][ldrow] = a4.z; As[ldk + 3][ldrow] = a4.w;
        Bs[ldk + 0][ldrow] = b4.x; Bs[ldk + 1][ldrow] = b4.y;
        Bs[ldk + 2][ldrow] = b4.z; Bs[ldk + 3][ldrow] = b4.w;
        __syncthreads();
#pragma unroll
        for (int k = 0; k < 8; ++k) {
            float ra[8], rb[8];
#pragma unroll
            for (int i = 0; i < 8; ++i) ra[i] = As[k][ty * 8 + i];
#pragma unroll
            for (int j = 0; j < 8; ++j) rb[j] = Bs[k][tx * 8 + j];
#pragma unroll
            for (int i = 0; i < 8; ++i)
#pragma unroll
                for (int j = 0; j < 8; ++j)
                    acc[i][j] += ra[i] * rb[j];
        }
        __syncthreads();
    }

    int mbase = bm * 128 + ty * 8;
    int nbase = bn * 128 + tx * 8;
#pragma unroll
    for (int i = 0; i < 8; ++i) {
        int m = mbase + i;
#pragma unroll
        for (int j = 0; j < 8; ++j) {
            int n = nbase + j;
            float v = acc[i][j];
            if (mode >= 1) v += bias[n];
            if (mode == 2) v += Add[(size_t)m * ldadd + n];
            if (mode == 3) {
                int b = m & 127, t = m >> 7;
                C[((size_t)b * TOUT + t) * ldc + n] = v;
            } else {
                C[(size_t)m * ldc + n] = v;
            }
        }
    }
}

// ---------------- small NT SGEMM: BM=BN=64, BK=16, 256 thr, 4x4 ------------
__global__ __launch_bounds__(256) void sgemm_nt_small(
    const float* __restrict__ A, int lda,
    const float* __restrict__ B, int ldb,
    float* __restrict__ C, int ldc, int K,
    const float* __restrict__ bias,
    const float* __restrict__ Add, int ldadd, int mode)
{
    __shared__ float As[16][64];
    __shared__ float Bs[16][64];
    int tid = threadIdx.x;
    int bn = blockIdx.x, bm = blockIdx.y;
    int ldrow = tid >> 2;
    int ldk   = (tid & 3) * 4;
    const float* Ap = A + (size_t)(bm * 64 + ldrow) * lda + ldk;
    const float* Bp = B + (size_t)(bn * 64 + ldrow) * ldb + ldk;
    int tx = tid & 15, ty = tid >> 4;
    float acc[4][4] = {};

    for (int k0 = 0; k0 < K; k0 += 16) {
        float4 a4 = *(const float4*)(Ap + k0);
        float4 b4 = *(const float4*)(Bp + k0);
        As[ldk + 0][ldrow] = a4.x; As[ldk + 1][ldrow] = a4.y;
        As[ldk + 2][ldrow] = a4.z; As[ldk + 3][ldrow] = a4.w;
        Bs[ldk + 0][ldrow] = b4.x; Bs[ldk + 1][ldrow] = b4.y;
        Bs[ldk + 2][ldrow] = b4.z; Bs[ldk + 3][ldrow] = b4.w;
        __syncthreads();
#pragma unroll
        for (int k = 0; k < 16; ++k) {
            float ra[4], rb[4];
#pragma unroll
            for (int i = 0; i < 4; ++i) ra[i] = As[k][ty * 4 + i];
#pragma unroll
            for (int j = 0; j < 4; ++j) rb[j] = Bs[k][tx * 4 + j];
#pragma unroll
            for (int i = 0; i < 4; ++i)
#pragma unroll
                for (int j = 0; j < 4; ++j)
                    acc[i][j] += ra[i] * rb[j];
        }
        __syncthreads();
    }

    int mbase = bm * 64 + ty * 4;
    int nbase = bn * 64 + tx * 4;
#pragma unroll
    for (int i = 0; i < 4; ++i) {
        int m = mbase + i;
#pragma unroll
        for (int j = 0; j < 4; ++j) {
            int n = nbase + j;
            float v = acc[i][j];
            if (mode >= 1) v += bias[n];
            if (mode == 2) v += Add[(size_t)m * ldadd + n];
            C[(size_t)m * ldc + n] = v;
        }
    }
}

// ---------------- embedding gather: xe[t*128+b, :] = emb[captions[b,t], :] --
__global__ void gather_embed(const int* __restrict__ captions,
                             const float* __restrict__ emb,
                             float* __restrict__ xe)
{
    int m = blockIdx.x;            // 0..1919 ; m = t*128 + b
    int t = m >> 7, b = m & 127;
    int cap = captions[b * TCAP + t];
    const float4* src = (const float4*)(emb + (size_t)cap * E_);
    float4* dst = (float4*)(xe + (size_t)m * E_);
    dst[threadIdx.x] = src[threadIdx.x];   // 128 threads * float4 = 512 floats
}

// ---------------- fused Bahdanau attention (one block per batch) -----------
__global__ __launch_bounds__(256) void attention_kernel(
    const float* __restrict__ q,       // (B,H)
    const float* __restrict__ keys,    // (B,S,H)
    const float* __restrict__ att_v,   // (H)
    const float* __restrict__ features,// (B,S,K)
    float* __restrict__ ctx)           // (B,K)
{
    __shared__ float qs[H_];
    __shared__ float av[H_];
    __shared__ float sc[S_];
    __shared__ float red[8];

    int b = blockIdx.x, tid = threadIdx.x;
    for (int i = tid; i < H_; i += 256) { qs[i] = q[b * H_ + i]; av[i] = att_v[i]; }
    __syncthreads();

    int warp = tid >> 5, lane = tid & 31;
    const float* kpb = keys + (size_t)b * S_ * H_;
    for (int s = warp; s < S_; s += 8) {
        const float* kps = kpb + (size_t)s * H_;
        float acc = 0.f;
        for (int h = lane; h < H_; h += 32)
            acc += av[h] * tanhf(qs[h] + kps[h]);
#pragma unroll
        for (int o = 16; o; o >>= 1) acc += __shfl_xor_sync(~0u, acc, o);
        if (!lane) sc[s] = acc;
    }
    __syncthreads();

    // softmax over S
    float m = -INFINITY;
    for (int s = tid; s < S_; s += 256) m = fmaxf(m, sc[s]);
#pragma unroll
    for (int o = 16; o; o >>= 1) m = fmaxf(m, __shfl_xor_sync(~0u, m, o));
    if (!lane) red[warp] = m;
    __syncthreads();
    m = red[0];
#pragma unroll
    for (int w = 1; w < 8; ++w) m = fmaxf(m, red[w]);
    __syncthreads();

    float ls = 0.f;
    for (int s = tid; s < S_; s += 256) { float e = expf(sc[s] - m); sc[s] = e; ls += e; }
#pragma unroll
    for (int o = 16; o; o >>= 1) ls += __shfl_xor_sync(~0u, ls, o);
    if (!lane) red[warp] = ls;
    __syncthreads();
    float sum = 0.f;
#pragma unroll
    for (int w = 0; w < 8; ++w) sum += red[w];
    float inv = 1.f / sum;

    // context: ctx[b,k] = sum_s w[s] * features[b,s,k]
    const float* fb = features + (size_t)b * S_ * K_;
    for (int k = tid; k < K_; k += 256) {
        float acc = 0.f;
        for (int s = 0; s < S_; ++s)
            acc += sc[s] * fb[(size_t)s * K_ + k];
        ctx[b * K_ + k] = acc * inv;
    }
}

// ---------------- GRU gates --------------------------------------------------
__global__ void gru_gate(const float* __restrict__ gi, const float* __restrict__ gh,
                         const float* __restrict__ hprev, float* __restrict__ hnew)
{
    int idx = blockIdx.x * blockDim.x + threadIdx.x;   // 0..65535
    int b = idx >> 9, j = idx & 511;
    int base = b * 1536 + j;
    float ir = gi[base], iz = gi[base + 512], in_ = gi[base + 1024];
    float hr = gh[base], hz = gh[base + 512], hn = gh[base + 1024];
    float r = 1.f / (1.f + expf(-(ir + hr)));
    float z = 1.f / (1.f + expf(-(iz + hz)));
    float n = tanhf(in_ + r * hn);
    hnew[idx] = (1.f - z) * n + z * hprev[idx];
}

__global__ void zero_kernel(float* p, int n)
{
    int idx = blockIdx.x * blockDim.x + threadIdx.x;
    if (idx < n) p[idx] = 0.f;
}

// ---------------- launch -----------------------------------------------------
extern "C" void kernel_launch(void* const* d_in, const int* in_sizes, int n_in,
                              void* d_out, int out_size)
{
    const float* features = (const float*)d_in[0];
    const int*   captions = (const int*)  d_in[1];
    const float* emb      = (const float*)d_in[2];
    const float* fc1_w    = (const float*)d_in[3];
    const float* fc1_b    = (const float*)d_in[4];
    const float* att_wq   = (const float*)d_in[5];
    const float* att_wk   = (const float*)d_in[6];
    const float* att_v    = (const float*)d_in[7];
    const float* fc0_w    = (const float*)d_in[8];
    const float* fc0_b    = (const float*)d_in[9];
    const float* gru_wih  = (const float*)d_in[10];
    const float* gru_whh  = (const float*)d_in[11];
    const float* gru_bih  = (const float*)d_in[12];
    const float* gru_bhh  = (const float*)d_in[13];
    const float* fc2_w    = (const float*)d_in[14];
    const float* fc2_b    = (const float*)d_in[15];
    float* out = (float*)d_out;

    float *keys, *xe, *x, *gix, *h, *q, *ctx, *ctxh, *gi, *gh;
    cudaGetSymbolAddress((void**)&keys, g_keys);
    cudaGetSymbolAddress((void**)&xe,   g_xe);
    cudaGetSymbolAddress((void**)&x,    g_x);
    cudaGetSymbolAddress((void**)&gix,  g_gix);
    cudaGetSymbolAddress((void**)&h,    g_h);
    cudaGetSymbolAddress((void**)&q,    g_q);
    cudaGetSymbolAddress((void**)&ctx,  g_ctx);
    cudaGetSymbolAddress((void**)&ctxh, g_ctxh);
    cudaGetSymbolAddress((void**)&gi,   g_gi);
    cudaGetSymbolAddress((void**)&gh,   g_gh);

    // --- prologue (everything hoisted out of the recurrence) ---
    gather_embed<<<TOUT * B_, 128>>>(captions, emb, xe);

    // fc1: x = xe @ fc1_w^T + fc1_b      (1920 x 512 x 512)
    sgemm_nt_big<<<dim3(H_ / 128, TOUT * B_ / 128), 256>>>(
        xe, E_, fc1_w, E_, x, H_, E_, fc1_b, nullptr, 0, 1);

    // keys_proj = features @ att_wk^T    (25088 x 512 x 512)
    sgemm_nt_big<<<dim3(H_ / 128, B_ * S_ / 128), 256>>>(
        features, K_, att_wk, K_, keys, H_, K_, nullptr, nullptr, 0, 0);

    // gix = x @ Wih[:, :H]^T             (1920 x 1536 x 512)
    sgemm_nt_big<<<dim3(3 * H_ / 128, TOUT * B_ / 128), 256>>>(
        x, H_, gru_wih, 2 * H_, gix, 3 * H_, H_, nullptr, nullptr, 0, 0);

    // h0 = 0
    zero_kernel<<<(B_ * H_ + 1023) / 1024, 1024>>>(h, B_ * H_);

    // --- recurrence (cheap part only) ---
    for (int t = 0; t < TOUT; ++t) {
        float* hprev = h + (size_t)t * B_ * H_;
        float* hnew  = h + (size_t)(t + 1) * B_ * H_;

        // q = h @ att_wq^T  (128 x 512 x 512)
        sgemm_nt_small<<<dim3(H_ / 64, B_ / 64), 256>>>(
            hprev, H_, att_wq, H_, q, H_, H_, nullptr, nullptr, 0, 0);

        attention_kernel<<<B_, 256>>>(q, keys, att_v, features, ctx);

        // ctxh = ctx @ fc0_w^T + fc0_b  (128 x 512 x 512)
        sgemm_nt_small<<<dim3(H_ / 64, B_ / 64), 256>>>(
            ctx, K_, fc0_w, K_, ctxh, H_, K_, fc0_b, nullptr, 0, 1);

        // gi = ctxh @ Wih[:, H:]^T + gix[t] + bih  (128 x 1536 x 512)
        sgemm_nt_small<<<dim3(3 * H_ / 64, B_ / 64), 256>>>(
            ctxh, H_, gru_wih + H_, 2 * H_, gi, 3 * H_, H_,
            gru_bih, gix + (size_t)t * B_ * 3 * H_, 3 * H_, 2);

        // gh = h @ Whh^T + bhh  (128 x 1536 x 512)
        sgemm_nt_small<<<dim3(3 * H_ / 64, B_ / 64), 256>>>(
            hprev, H_, gru_whh, H_, gh, 3 * H_, H_, gru_bhh, nullptr, 0, 1);

        gru_gate<<<B_ * H_ / 1024, 1024>>>(gi, gh, hprev, hnew);
    }

    // --- epilogue: all 15 logit GEMMs batched as one (1920 x 32000 x 512) ---
    sgemm_nt_big<<<dim3(V_ / 128, TOUT * B_ / 128), 256>>>(
        h + (size_t)B_ * H_, H_, fc2_w, H_, out, V_, H_,
        fc2_b, nullptr, 0, 3);
}

// round 2
// speedup vs baseline: 2.9384x; 2.9384x over previous
#include <cuda_runtime.h>
#include <cuda_fp16.h>
#include <cuda_bf16.h>
#include <math.h>
#include <stdint.h>

// Problem dims
#define B_   128
#define S_   196
#define K_   512
#define TCAP 16
#define TOUT 15
#define V_   32000
#define E_   512
#define H_   512

// ---------------- scratch (device globals; allocation-free) ----------------
__device__ float g_keys[(size_t)B_ * S_ * H_];     // keys_proj (B,S,H) fp32
__device__ float g_gix[TOUT * B_ * 3 * H_];        // x_t @ Wx^T  (t*128+b, 1536)
__device__ float g_h[(TOUT + 1) * B_ * H_];        // h_0..h_15
__device__ float g_qgh[B_ * 2048];                 // per-step [q | gh]
__device__ float g_ctx[B_ * K_];
__device__ float g_gi[B_ * 3 * H_];
__device__ float g_wcat[2048 * 512];               // [att_wq ; gru_whh]
__device__ float g_bcat[2048];                     // [0 ; gru_bhh]
__device__ float g_wprime[1536 * 512];             // Wih_ctx @ fc0_w
__device__ float g_bias2[1536];                    // Wih_ctx@fc0_b + b_ih
__device__ float g_fc0wT[512 * 512];

// fp16 operands
__device__ __half g_xe_h[TOUT * B_ * E_];
__device__ __half g_x_h[TOUT * B_ * H_];
__device__ __half g_fc1w_h[H_ * E_];
__device__ __half g_wk_h[H_ * K_];
__device__ __half g_feat_h[(size_t)B_ * S_ * K_];
__device__ __half g_wihx_h[1536 * 512];
__device__ __half g_fc2w_h[(size_t)V_ * H_];
__device__ __half g_h_h[TOUT * B_ * H_];

// ========================= fp16 tensor-core NT GEMM ========================
// C[M,N] = A[M,K]h * B[N,K]h^T ; BM=BN=128, BK=32, 256 thr, 8 warps (2m x 4n)
// warp tile 64x32 ; mma.m16n8k16 ; modes: 0 plain f32, 1 +bias f32,
// 3 +bias remap (m=t*128+b -> row b*15+t), 4 +bias store fp16
__device__ __forceinline__ void ldsm4(uint32_t* r, uint32_t addr) {
    asm volatile("ldmatrix.sync.aligned.m8n8.x4.shared.b16 {%0,%1,%2,%3}, [%4];"
        : "=r"(r[0]), "=r"(r[1]), "=r"(r[2]), "=r"(r[3]) : "r"(addr));
}
__device__ __forceinline__ void mma16816(float* c, const uint32_t* a, const uint32_t* b) {
    asm volatile("mma.sync.aligned.m16n8k16.row.col.f32.f16.f16.f32 "
        "{%0,%1,%2,%3}, {%4,%5,%6,%7}, {%8,%9}, {%0,%1,%2,%3};"
        : "+f"(c[0]), "+f"(c[1]), "+f"(c[2]), "+f"(c[3])
        : "r"(a[0]), "r"(a[1]), "r"(a[2]), "r"(a[3]), "r"(b[0]), "r"(b[1]));
}

__global__ __launch_bounds__(256) void hgemm_nt(
    const __half* __restrict__ A, int lda,
    const __half* __restrict__ B, int ldb,
    void* __restrict__ Cv, int ldc, int K,
    const float* __restrict__ bias, int mode)
{
    __shared__ __half As[2][128][40];
    __shared__ __half Bs[2][128][40];
    int tid = threadIdx.x, lane = tid & 31, warp = tid >> 5;
    int wm = warp & 1, wn = warp >> 1;
    int bn = blockIdx.x, bm = blockIdx.y;

    int r0 = tid >> 2, r1 = r0 + 64;
    int kc = (tid & 3) * 8;
    const __half* Ap0 = A + (size_t)(bm * 128 + r0) * lda + kc;
    const __half* Ap1 = A + (size_t)(bm * 128 + r1) * lda + kc;
    const __half* Bp0 = B + (size_t)(bn * 128 + r0) * ldb + kc;
    const __half* Bp1 = B + (size_t)(bn * 128 + r1) * ldb + kc;

    float acc[4][4][4] = {};
    int a_r = ((lane >> 3) & 1) * 8 + (lane & 7);
    int a_c = (lane >> 4) * 8;
    int b_r = ((lane >> 4) & 1) * 8 + (lane & 7);
    int b_c = ((lane >> 3) & 1) * 8;

    uint4 av0 = *(const uint4*)(Ap0);
    uint4 av1 = *(const uint4*)(Ap1);
    uint4 bv0 = *(const uint4*)(Bp0);
    uint4 bv1 = *(const uint4*)(Bp1);
    *(uint4*)&As[0][r0][kc] = av0; *(uint4*)&As[0][r1][kc] = av1;
    *(uint4*)&Bs[0][r0][kc] = bv0; *(uint4*)&Bs[0][r1][kc] = bv1;
    __syncthreads();

    int nkt = K / 32, cur = 0;
    for (int kt = 0; kt < nkt; ++kt) {
        if (kt + 1 < nkt) {
            av0 = *(const uint4*)(Ap0 + (kt + 1) * 32);
            av1 = *(const uint4*)(Ap1 + (kt + 1) * 32);
            bv0 = *(const uint4*)(Bp0 + (kt + 1) * 32);
            bv1 = *(const uint4*)(Bp1 + (kt + 1) * 32);
        }
        uint32_t as_base = (uint32_t)__cvta_generic_to_shared(&As[cur][0][0]);
        uint32_t bs_base = (uint32_t)__cvta_generic_to_shared(&Bs[cur][0][0]);
#pragma unroll
        for (int ks = 0; ks < 2; ++ks) {
            int k = ks * 16;
            uint32_t af[4][4], bf[4][2];
#pragma unroll
            for (int mi = 0; mi < 4; ++mi) {
                uint32_t addr = as_base +
                    (uint32_t)(((wm * 64 + mi * 16 + a_r) * 40 + k + a_c) * 2);
                ldsm4(af[mi], addr);
            }
#pragma unroll
            for (int nh = 0; nh < 2; ++nh) {
                uint32_t r[4];
                uint32_t addr = bs_base +
                    (uint32_t)(((wn * 32 + nh * 16 + b_r) * 40 + k + b_c) * 2);
                ldsm4(r, addr);
                bf[2 * nh + 0][0] = r[0]; bf[2 * nh + 0][1] = r[1];
                bf[2 * nh + 1][0] = r[2]; bf[2 * nh + 1][1] = r[3];
            }
#pragma unroll
            for (int mi = 0; mi < 4; ++mi)
#pragma unroll
                for (int ni = 0; ni < 4; ++ni)
                    mma16816(acc[mi][ni], af[mi], bf[ni]);
        }
        if (kt + 1 < nkt) {
            __syncthreads();
            cur ^= 1;
            *(uint4*)&As[cur][r0][kc] = av0; *(uint4*)&As[cur][r1][kc] = av1;
            *(uint4*)&Bs[cur][r0][kc] = bv0; *(uint4*)&Bs[cur][r1][kc] = bv1;
            __syncthreads();
        }
    }

    // epilogue
    int mb = bm * 128 + wm * 64;
    int nb = bn * 128 + wn * 32;
    int qr = lane >> 2, qc = (lane & 3) * 2;
#pragma unroll
    for (int mi = 0; mi < 4; ++mi) {
#pragma unroll
        for (int ni = 0; ni < 4; ++ni) {
            int n = nb + ni * 8 + qc;
            float bv = 0.f, bv2 = 0.f;
            if (mode != 0) { bv = bias[n]; bv2 = bias[n + 1]; }
            float* c4 = acc[mi][ni];
#pragma unroll
            for (int half_ = 0; half_ < 2; ++half_) {
                int m = mb + mi * 16 + qr + half_ * 8;
                float v0 = c4[half_ * 2 + 0] + bv;
                float v1 = c4[half_ * 2 + 1] + bv2;
                if (mode == 4) {
                    __half* C = (__half*)Cv;
                    *(__half2*)&C[(size_t)m * ldc + n] =
                        __halves2half2(__float2half(v0), __float2half(v1));
                } else if (mode == 3) {
                    int b = m & 127, t = m >> 7;
                    float* C = (float*)Cv;
                    *(float2*)&C[((size_t)b * TOUT + t) * ldc + n] = make_float2(v0, v1);
                } else {
                    float* C = (float*)Cv;
                    *(float2*)&C[(size_t)m * ldc + n] = make_float2(v0, v1);
                }
            }
        }
    }
}

// ---------------- fp32 NT SGEMM (prologue W' + per-step) -------------------
__global__ __launch_bounds__(256) void sgemm_nt_big(
    const float* __restrict__ A, int lda,
    const float* __restrict__ B, int ldb,
    float* __restrict__ C, int ldc, int K,
    const float* __restrict__ bias,
    const float* __restrict__ Add, int ldadd, int mode)
{
    __shared__ float As[8][128];
    __shared__ float Bs[8][128];
    int tid = threadIdx.x;
    int bn = blockIdx.x, bm = blockIdx.y;
    int ldrow = tid >> 1;
    int ldk   = (tid & 1) * 4;
    const float* Ap = A + (size_t)(bm * 128 + ldrow) * lda + ldk;
    const float* Bp = B + (size_t)(bn * 128 + ldrow) * ldb + ldk;
    int tx = tid & 15, ty = tid >> 4;
    float acc[8][8] = {};

    for (int k0 = 0; k0 < K; k0 += 8) {
        float4 a4 = *(const float4*)(Ap + k0);
        float4 b4 = *(const float4*)(Bp + k0);
        As[ldk + 0][ldrow] = a4.x; As[ldk + 1][ldrow] = a4.y;
        As[ldk + 2][ldrow] = a4.z; As[ldk + 3][ldrow] = a4.w;
        Bs[ldk + 0][ldrow] = b4.x; Bs[ldk + 1][ldrow] = b4.y;
        Bs[ldk + 2][ldrow] = b4.z; Bs[ldk + 3][ldrow] = b4.w;
        __syncthreads();
#pragma unroll
        for (int k = 0; k < 8; ++k) {
            float ra[8], rb[8];
#pragma unroll
            for (int i = 0; i < 8; ++i) ra[i] = As[k][ty * 8 + i];
#pragma unroll
            for (int j = 0; j < 8; ++j) rb[j] = Bs[k][tx * 8 + j];
#pragma unroll
            for (int i = 0; i < 8; ++i)
#pragma unroll
                for (int j = 0; j < 8; ++j)
                    acc[i][j] += ra[i] * rb[j];
        }
        __syncthreads();
    }
    int mbase = bm * 128 + ty * 8;
    int nbase = bn * 128 + tx * 8;
#pragma unroll
    for (int i = 0; i < 8; ++i) {
        int m = mbase + i;
#pragma unroll
        for (int j = 0; j < 8; ++j) {
            int n = nbase + j;
            float v = acc[i][j];
            if (mode >= 1) v += bias[n];
            if (mode == 2) v += Add[(size_t)m * ldadd + n];
            C[(size_t)m * ldc + n] = v;
        }
    }
}

__global__ __launch_bounds__(256) void sgemm_nt_small(
    const float* __restrict__ A, int lda,
    const float* __restrict__ B, int ldb,
    float* __restrict__ C, int ldc, int K,
    const float* __restrict__ bias,
    const float* __restrict__ Add, int ldadd, int mode)
{
    __shared__ float As[16][64];
    __shared__ float Bs[16][64];
    int tid = threadIdx.x;
    int bn = blockIdx.x, bm = blockIdx.y;
    int ldrow = tid >> 2;
    int ldk   = (tid & 3) * 4;
    const float* Ap = A + (size_t)(bm * 64 + ldrow) * lda + ldk;
    const float* Bp = B + (size_t)(bn * 64 + ldrow) * ldb + ldk;
    int tx = tid & 15, ty = tid >> 4;
    float acc[4][4] = {};

    for (int k0 = 0; k0 < K; k0 += 16) {
        float4 a4 = *(const float4*)(Ap + k0);
        float4 b4 = *(const float4*)(Bp + k0);
        As[ldk + 0][ldrow] = a4.x; As[ldk + 1][ldrow] = a4.y;
        As[ldk + 2][ldrow] = a4.z; As[ldk + 3][ldrow] = a4.w;
        Bs[ldk + 0][ldrow] = b4.x; Bs[ldk + 1][ldrow] = b4.y;
        Bs[ldk + 2][ldrow] = b4.z; Bs[ldk + 3][ldrow] = b4.w;
        __syncthreads();
#pragma unroll
        for (int k = 0; k < 16; ++k) {
            float ra[4], rb[4];
#pragma unroll
            for (int i = 0; i < 4; ++i) ra[i] = As[k][ty * 4 + i];
#pragma unroll
            for (int j = 0; j < 4; ++j) rb[j] = Bs[k][tx * 4 + j];
#pragma unroll
            for (int i = 0; i < 4; ++i)
#pragma unroll
                for (int j = 0; j < 4; ++j)
                    acc[i][j] += ra[i] * rb[j];
        }
        __syncthreads();
    }
    int mbase = bm * 64 + ty * 4;
    int nbase = bn * 64 + tx * 4;
#pragma unroll
    for (int i = 0; i < 4; ++i) {
        int m = mbase + i;
#pragma unroll
        for (int j = 0; j < 4; ++j) {
            int n = nbase + j;
            float v = acc[i][j];
            if (mode >= 1) v += bias[n];
            if (mode == 2) v += Add[(size_t)m * ldadd + n];
            C[(size_t)m * ldc + n] = v;
        }
    }
}

// -------- embedding gather -> fp16 -----------------------------------------
__global__ void gather_embed_h(const int* __restrict__ captions,
                               const float* __restrict__ emb,
                               __half* __restrict__ xe)
{
    int m = blockIdx.x;            // m = t*128 + b
    int t = m >> 7, b = m & 127;
    int cap = captions[b * TCAP + t];
    float4 v = ((const float4*)(emb + (size_t)cap * E_))[threadIdx.x];
    __half2* dst = (__half2*)(xe + (size_t)m * E_);
    dst[2 * threadIdx.x + 0] = __floats2half2_rn(v.x, v.y);
    dst[2 * threadIdx.x + 1] = __floats2half2_rn(v.z, v.w);
}

// -------- generic f32 -> f16 (n % 4 == 0) -----------------------------------
__global__ void f2h(const float* __restrict__ in, __half* __restrict__ out, int n)
{
    int i = (blockIdx.x * blockDim.x + threadIdx.x) * 4;
    if (i < n) {
        float4 v = *(const float4*)(in + i);
        ((__half2*)(out + i))[0] = __floats2half2_rn(v.x, v.y);
        ((__half2*)(out + i))[1] = __floats2half2_rn(v.z, v.w);
    }
}

// -------- gru_wih[:, :512] -> fp16 compact ----------------------------------
__global__ void conv_wihx(const float* __restrict__ wih, __half* __restrict__ out)
{
    int n = blockIdx.x;            // 0..1535
    int t = threadIdx.x;           // 0..127
    float4 v = *(const float4*)(wih + (size_t)n * 1024 + t * 4);
    __half2* o = (__half2*)(out + (size_t)n * 512 + t * 4);
    o[0] = __floats2half2_rn(v.x, v.y);
    o[1] = __floats2half2_rn(v.z, v.w);
}

// -------- 512x512 transpose --------------------------------------------------
__global__ void transpose512(const float* __restrict__ in, float* __restrict__ out)
{
    __shared__ float tile[32][33];
    int x = blockIdx.x * 32 + threadIdx.x;
    int y = blockIdx.y * 32 + threadIdx.y;
#pragma unroll
    for (int j = 0; j < 4; ++j)
        tile[threadIdx.y + 8 * j][threadIdx.x] = in[(size_t)(y + 8 * j) * 512 + x];
    __syncthreads();
    int x2 = blockIdx.y * 32 + threadIdx.x;
    int y2 = blockIdx.x * 32 + threadIdx.y;
#pragma unroll
    for (int j = 0; j < 4; ++j)
        out[(size_t)(y2 + 8 * j) * 512 + x2] = tile[threadIdx.x][threadIdx.y + 8 * j];
}

// -------- bias2 = Wih_ctx @ fc0_b + b_ih ------------------------------------
__global__ void bias2_kernel(const float* __restrict__ wih, const float* __restrict__ fc0b,
                             const float* __restrict__ bih, float* __restrict__ out)
{
    int n = blockIdx.x * blockDim.x + threadIdx.x;
    if (n < 1536) {
        float s = 0.f;
        for (int j = 0; j < 512; ++j) s += wih[(size_t)n * 1024 + 512 + j] * fc0b[j];
        out[n] = s + bih[n];
    }
}

__global__ void bcat_kernel(const float* __restrict__ bhh, float* __restrict__ out)
{
    int j = blockIdx.x * blockDim.x + threadIdx.x;
    if (j < 2048) out[j] = (j < 512) ? 0.f : bhh[j - 512];
}

// -------- fused Bahdanau attention ------------------------------------------
__global__ __launch_bounds__(256) void attention_kernel(
    const float* __restrict__ qgh,     // (B, 2048): q is cols [0,512)
    const float* __restrict__ keys,    // (B,S,H)
    const float* __restrict__ att_v,   // (H)
    const float* __restrict__ features,// (B,S,K)
    float* __restrict__ ctx)           // (B,K)
{
    __shared__ float qs[H_];
    __shared__ float av[H_];
    __shared__ float sc[S_];
    __shared__ float red[8];

    int b = blockIdx.x, tid = threadIdx.x;
    for (int i = tid; i < H_; i += 256) { qs[i] = qgh[b * 2048 + i]; av[i] = att_v[i]; }
    __syncthreads();

    int warp = tid >> 5, lane = tid & 31;
    const float* kpb = keys + (size_t)b * S_ * H_;
    for (int s = warp; s < S_; s += 8) {
        const float* kps = kpb + (size_t)s * H_;
        float acc = 0.f;
        for (int h = lane; h < H_; h += 32)
            acc += av[h] * tanhf(qs[h] + kps[h]);
#pragma unroll
        for (int o = 16; o; o >>= 1) acc += __shfl_xor_sync(~0u, acc, o);
        if (!lane) sc[s] = acc;
    }
    __syncthreads();

    float m = -INFINITY;
    for (int s = tid; s < S_; s += 256) m = fmaxf(m, sc[s]);
#pragma unroll
    for (int o = 16; o; o >>= 1) m = fmaxf(m, __shfl_xor_sync(~0u, m, o));
    if (!lane) red[warp] = m;
    __syncthreads();
    m = red[0];
#pragma unroll
    for (int w = 1; w < 8; ++w) m = fmaxf(m, red[w]);
    __syncthreads();

    float ls = 0.f;
    for (int s = tid; s < S_; s += 256) { float e = expf(sc[s] - m); sc[s] = e; ls += e; }
#pragma unroll
    for (int o = 16; o; o >>= 1) ls += __shfl_xor_sync(~0u, ls, o);
    if (!lane) red[warp] = ls;
    __syncthreads();
    float sum = 0.f;
#pragma unroll
    for (int w = 0; w < 8; ++w) sum += red[w];
    float inv = 1.f / sum;

    const float* fb = features + (size_t)b * S_ * K_;
    for (int k = tid; k < K_; k += 256) {
        float acc = 0.f;
        for (int s = 0; s < S_; ++s)
            acc += sc[s] * fb[(size_t)s * K_ + k];
        ctx[b * K_ + k] = acc * inv;
    }
}

// -------- GRU gates ----------------------------------------------------------
__global__ void gru_gate(const float* __restrict__ gi, const float* __restrict__ qgh,
                         const float* __restrict__ hprev, float* __restrict__ hnew)
{
    int idx = blockIdx.x * blockDim.x + threadIdx.x;   // 0..65535
    int b = idx >> 9, j = idx & 511;
    const float* ghb = qgh + (size_t)b * 2048 + 512;
    int base = b * 1536 + j;
    float ir = gi[base], iz = gi[base + 512], in_ = gi[base + 1024];
    float hr = ghb[j], hz = ghb[512 + j], hn = ghb[1024 + j];
    float r = 1.f / (1.f + expf(-(ir + hr)));
    float z = 1.f / (1.f + expf(-(iz + hz)));
    float n = tanhf(in_ + r * hn);
    hnew[idx] = (1.f - z) * n + z * hprev[idx];
}

__global__ void zero_kernel(float* p, int n)
{
    int idx = blockIdx.x * blockDim.x + threadIdx.x;
    if (idx < n) p[idx] = 0.f;
}

// ---------------- launch -----------------------------------------------------
extern "C" void kernel_launch(void* const* d_in, const int* in_sizes, int n_in,
                              void* d_out, int out_size)
{
    const float* features = (const float*)d_in[0];
    const int*   captions = (const int*)  d_in[1];
    const float* emb      = (const float*)d_in[2];
    const float* fc1_w    = (const float*)d_in[3];
    const float* fc1_b    = (const float*)d_in[4];
    const float* att_wq   = (const float*)d_in[5];
    const float* att_wk   = (const float*)d_in[6];
    const float* att_v    = (const float*)d_in[7];
    const float* fc0_w    = (const float*)d_in[8];
    const float* fc0_b    = (const float*)d_in[9];
    const float* gru_wih  = (const float*)d_in[10];
    const float* gru_whh  = (const float*)d_in[11];
    const float* gru_bih  = (const float*)d_in[12];
    const float* gru_bhh  = (const float*)d_in[13];
    const float* fc2_w    = (const float*)d_in[14];
    const float* fc2_b    = (const float*)d_in[15];
    float* out = (float*)d_out;

    float *keys, *gix, *h, *qgh, *ctx, *gi, *wcat, *bcat, *wprime, *bias2, *fc0wT;
    __half *xe_h, *x_h, *fc1w_h, *wk_h, *feat_h, *wihx_h, *fc2w_h, *h_h;
    cudaGetSymbolAddress((void**)&keys,   g_keys);
    cudaGetSymbolAddress((void**)&gix,    g_gix);
    cudaGetSymbolAddress((void**)&h,      g_h);
    cudaGetSymbolAddress((void**)&qgh,    g_qgh);
    cudaGetSymbolAddress((void**)&ctx,    g_ctx);
    cudaGetSymbolAddress((void**)&gi,     g_gi);
    cudaGetSymbolAddress((void**)&wcat,   g_wcat);
    cudaGetSymbolAddress((void**)&bcat,   g_bcat);
    cudaGetSymbolAddress((void**)&wprime, g_wprime);
    cudaGetSymbolAddress((void**)&bias2,  g_bias2);
    cudaGetSymbolAddress((void**)&fc0wT,  g_fc0wT);
    cudaGetSymbolAddress((void**)&xe_h,   g_xe_h);
    cudaGetSymbolAddress((void**)&x_h,    g_x_h);
    cudaGetSymbolAddress((void**)&fc1w_h, g_fc1w_h);
    cudaGetSymbolAddress((void**)&wk_h,   g_wk_h);
    cudaGetSymbolAddress((void**)&feat_h, g_feat_h);
    cudaGetSymbolAddress((void**)&wihx_h, g_wihx_h);
    cudaGetSymbolAddress((void**)&fc2w_h, g_fc2w_h);
    cudaGetSymbolAddress((void**)&h_h,    g_h_h);

    // ---- conversions & prologue precomputes ----
    gather_embed_h<<<TOUT * B_, 128>>>(captions, emb, xe_h);
    f2h<<<(H_ * E_ / 4 + 255) / 256, 256>>>(fc1_w, fc1w_h, H_ * E_);
    f2h<<<(H_ * K_ / 4 + 255) / 256, 256>>>(att_wk, wk_h, H_ * K_);
    f2h<<<(B_ * S_ * K_ / 4 + 255) / 256, 256>>>(features, feat_h, B_ * S_ * K_);
    f2h<<<(V_ * H_ / 4 + 255) / 256, 256>>>(fc2_w, fc2w_h, V_ * H_);
    conv_wihx<<<1536, 128>>>(gru_wih, wihx_h);
    transpose512<<<dim3(16, 16), dim3(32, 8)>>>(fc0_w, fc0wT);
    bias2_kernel<<<12, 128>>>(gru_wih, fc0_b, gru_bih, bias2);
    bcat_kernel<<<8, 256>>>(gru_bhh, bcat);
    cudaMemcpyAsync(wcat, att_wq, (size_t)512 * 512 * 4, cudaMemcpyDeviceToDevice);
    cudaMemcpyAsync(wcat + 512 * 512, gru_whh, (size_t)1536 * 512 * 4, cudaMemcpyDeviceToDevice);

    // fc1: x_h = fp16(xe @ fc1_w^T + b)           (1920 x 512 x 512)
    hgemm_nt<<<dim3(H_ / 128, TOUT * B_ / 128), 256>>>(
        xe_h, E_, fc1w_h, E_, x_h, H_, E_, fc1_b, 4);
    // keys_proj = features @ att_wk^T (fp32 out)  (25088 x 512 x 512)
    hgemm_nt<<<dim3(H_ / 128, B_ * S_ / 128), 256>>>(
        feat_h, K_, wk_h, K_, keys, H_, K_, nullptr, 0);
    // gix = x @ Wih_x^T (fp32 out)                (1920 x 1536 x 512)
    hgemm_nt<<<dim3(3 * H_ / 128, TOUT * B_ / 128), 256>>>(
        x_h, H_, wihx_h, H_, gix, 3 * H_, H_, nullptr, 0);
    // W' = Wih_ctx @ fc0_w  (fp32, via fc0_w^T)   (1536 x 512 x 512)
    sgemm_nt_big<<<dim3(4, 12), 256>>>(
        gru_wih + 512, 1024, fc0wT, 512, wprime, 512, 512, nullptr, nullptr, 0, 0);

    zero_kernel<<<(B_ * H_ + 1023) / 1024, 1024>>>(h, B_ * H_);

    // ---- recurrence ----
    for (int t = 0; t < TOUT; ++t) {
        float* hprev = h + (size_t)t * B_ * H_;
        float* hnew  = h + (size_t)(t + 1) * B_ * H_;

        // [q | gh] = h @ [Wq ; Whh]^T + [0 ; bhh]   (128 x 2048 x 512)
        sgemm_nt_small<<<dim3(2048 / 64, B_ / 64), 256>>>(
            hprev, H_, wcat, 512, qgh, 2048, 512, bcat, nullptr, 0, 1);

        attention_kernel<<<B_, 256>>>(qgh, keys, att_v, features, ctx);

        // gi = ctx @ W'^T + bias2 + gix_t           (128 x 1536 x 512)
        sgemm_nt_small<<<dim3(1536 / 64, B_ / 64), 256>>>(
            ctx, K_, wprime, 512, gi, 1536, 512,
            bias2, gix + (size_t)t * B_ * 3 * H_, 1536, 2);

        gru_gate<<<B_ * H_ / 1024, 1024>>>(gi, qgh, hprev, hnew);
    }

    // ---- logits: fp16 tensor GEMM (1920 x 32000 x 512), remap + bias ----
    f2h<<<(TOUT * B_ * H_ / 4 + 255) / 256, 256>>>(h + B_ * H_, h_h, TOUT * B_ * H_);
    hgemm_nt<<<dim3(V_ / 128, TOUT * B_ / 128), 256>>>(
        h_h, H_, fc2w_h, H_, out, V_, H_, fc2_b, 3);
}

// round 3
// speedup vs baseline: 5.6524x; 1.9236x over previous
#include <cuda_runtime.h>
#include <cuda_fp16.h>
#include <cuda_bf16.h>
#include <math.h>
#include <stdint.h>

// Problem dims
#define B_   128
#define S_   196
#define K_   512
#define TCAP 16
#define TOUT 15
#define V_   32000
#define E_   512
#define H_   512

// ---------------- scratch (device globals; allocation-free) ----------------
__device__ float g_gix[TOUT * B_ * 3 * H_];        // x_t @ Wx^T  (t*128+b, 1536)
__device__ float g_h[(TOUT + 1) * B_ * H_];        // h_0..h_15 fp32 master
__device__ float g_qgh[B_ * 2048];                 // per-step [q | gh]
__device__ float g_gi[B_ * 3 * H_];
__device__ float g_bcat[2048];                     // [0 ; gru_bhh]
__device__ float g_wprime[1536 * 512];             // Wih_ctx @ fc0_w (fp32)
__device__ float g_bias2[1536];                    // Wih_ctx@fc0_b + b_ih
__device__ float g_fc0wT[512 * 512];

// fp16 operands
__device__ __half g_xe_h[TOUT * B_ * E_];
__device__ __half g_x_h[TOUT * B_ * H_];
__device__ __half g_fc1w_h[H_ * E_];
__device__ __half g_wk_h[H_ * K_];
__device__ __half g_feat_h[(size_t)B_ * S_ * K_];
__device__ __half g_keys_h[(size_t)B_ * S_ * H_];
__device__ __half g_wihx_h[1536 * 512];
__device__ __half g_fc2w_h[(size_t)V_ * H_];
__device__ __half g_h16[(TOUT + 1) * B_ * H_];     // fp16 h, slot 0 = zeros
__device__ __half g_ctx_h[B_ * K_];
__device__ __half g_wcat_h[2048 * 512];            // [att_wq ; gru_whh] fp16
__device__ __half g_wprime_h[1536 * 512];

// ========================= mma helpers =====================================
__device__ __forceinline__ void ldsm4(uint32_t* r, uint32_t addr) {
    asm volatile("ldmatrix.sync.aligned.m8n8.x4.shared.b16 {%0,%1,%2,%3}, [%4];"
        : "=r"(r[0]), "=r"(r[1]), "=r"(r[2]), "=r"(r[3]) : "r"(addr));
}
__device__ __forceinline__ void mma16816(float* c, const uint32_t* a, const uint32_t* b) {
    asm volatile("mma.sync.aligned.m16n8k16.row.col.f32.f16.f16.f32 "
        "{%0,%1,%2,%3}, {%4,%5,%6,%7}, {%8,%9}, {%0,%1,%2,%3};"
        : "+f"(c[0]), "+f"(c[1]), "+f"(c[2]), "+f"(c[3])
        : "r"(a[0]), "r"(a[1]), "r"(a[2]), "r"(a[3]), "r"(b[0]), "r"(b[1]));
}

// ========================= fp16 tensor-core NT GEMM (big) ==================
// C[M,N] = A[M,K]h * B[N,K]h^T ; BM=BN=128, BK=32, 256 thr, 8 warps (2m x 4n)
// modes: 0 plain f32, 1 +bias f32, 3 +bias remap (m=t*128+b -> row b*15+t),
//        4 +bias store fp16, 5 plain store fp16
__global__ __launch_bounds__(256) void hgemm_nt(
    const __half* __restrict__ A, int lda,
    const __half* __restrict__ B, int ldb,
    void* __restrict__ Cv, int ldc, int K,
    const float* __restrict__ bias, int mode)
{
    __shared__ __half As[2][128][40];
    __shared__ __half Bs[2][128][40];
    int tid = threadIdx.x, lane = tid & 31, warp = tid >> 5;
    int wm = warp & 1, wn = warp >> 1;
    int bn = blockIdx.x, bm = blockIdx.y;

    int r0 = tid >> 2, r1 = r0 + 64;
    int kc = (tid & 3) * 8;
    const __half* Ap0 = A + (size_t)(bm * 128 + r0) * lda + kc;
    const __half* Ap1 = A + (size_t)(bm * 128 + r1) * lda + kc;
    const __half* Bp0 = B + (size_t)(bn * 128 + r0) * ldb + kc;
    const __half* Bp1 = B + (size_t)(bn * 128 + r1) * ldb + kc;

    float acc[4][4][4] = {};
    int a_r = ((lane >> 3) & 1) * 8 + (lane & 7);
    int a_c = (lane >> 4) * 8;
    int b_r = ((lane >> 4) & 1) * 8 + (lane & 7);
    int b_c = ((lane >> 3) & 1) * 8;

    uint4 av0 = *(const uint4*)(Ap0);
    uint4 av1 = *(const uint4*)(Ap1);
    uint4 bv0 = *(const uint4*)(Bp0);
    uint4 bv1 = *(const uint4*)(Bp1);
    *(uint4*)&As[0][r0][kc] = av0; *(uint4*)&As[0][r1][kc] = av1;
    *(uint4*)&Bs[0][r0][kc] = bv0; *(uint4*)&Bs[0][r1][kc] = bv1;
    __syncthreads();

    int nkt = K / 32, cur = 0;
    for (int kt = 0; kt < nkt; ++kt) {
        if (kt + 1 < nkt) {
            av0 = *(const uint4*)(Ap0 + (kt + 1) * 32);
            av1 = *(const uint4*)(Ap1 + (kt + 1) * 32);
            bv0 = *(const uint4*)(Bp0 + (kt + 1) * 32);
            bv1 = *(const uint4*)(Bp1 + (kt + 1) * 32);
        }
        uint32_t as_base = (uint32_t)__cvta_generic_to_shared(&As[cur][0][0]);
        uint32_t bs_base = (uint32_t)__cvta_generic_to_shared(&Bs[cur][0][0]);
#pragma unroll
        for (int ks = 0; ks < 2; ++ks) {
            int k = ks * 16;
            uint32_t af[4][4], bf[4][2];
#pragma unroll
            for (int mi = 0; mi < 4; ++mi) {
                uint32_t addr = as_base +
                    (uint32_t)(((wm * 64 + mi * 16 + a_r) * 40 + k + a_c) * 2);
                ldsm4(af[mi], addr);
            }
#pragma unroll
            for (int nh = 0; nh < 2; ++nh) {
                uint32_t r[4];
                uint32_t addr = bs_base +
                    (uint32_t)(((wn * 32 + nh * 16 + b_r) * 40 + k + b_c) * 2);
                ldsm4(r, addr);
                bf[2 * nh + 0][0] = r[0]; bf[2 * nh + 0][1] = r[1];
                bf[2 * nh + 1][0] = r[2]; bf[2 * nh + 1][1] = r[3];
            }
#pragma unroll
            for (int mi = 0; mi < 4; ++mi)
#pragma unroll
                for (int ni = 0; ni < 4; ++ni)
                    mma16816(acc[mi][ni], af[mi], bf[ni]);
        }
        if (kt + 1 < nkt) {
            __syncthreads();
            cur ^= 1;
            *(uint4*)&As[cur][r0][kc] = av0; *(uint4*)&As[cur][r1][kc] = av1;
            *(uint4*)&Bs[cur][r0][kc] = bv0; *(uint4*)&Bs[cur][r1][kc] = bv1;
            __syncthreads();
        }
    }

    int mb = bm * 128 + wm * 64;
    int nb = bn * 128 + wn * 32;
    int qr = lane >> 2, qc = (lane & 3) * 2;
#pragma unroll
    for (int mi = 0; mi < 4; ++mi) {
#pragma unroll
        for (int ni = 0; ni < 4; ++ni) {
            int n = nb + ni * 8 + qc;
            float bv = 0.f, bv2 = 0.f;
            if (mode != 0 && mode != 5) { bv = bias[n]; bv2 = bias[n + 1]; }
            float* c4 = acc[mi][ni];
#pragma unroll
            for (int half_ = 0; half_ < 2; ++half_) {
                int m = mb + mi * 16 + qr + half_ * 8;
                float v0 = c4[half_ * 2 + 0] + bv;
                float v1 = c4[half_ * 2 + 1] + bv2;
                if (mode == 4 || mode == 5) {
                    __half* C = (__half*)Cv;
                    *(__half2*)&C[(size_t)m * ldc + n] =
                        __halves2half2(__float2half(v0), __float2half(v1));
                } else if (mode == 3) {
                    int b = m & 127, t = m >> 7;
                    float* C = (float*)Cv;
                    *(float2*)&C[((size_t)b * TOUT + t) * ldc + n] = make_float2(v0, v1);
                } else {
                    float* C = (float*)Cv;
                    *(float2*)&C[(size_t)m * ldc + n] = make_float2(v0, v1);
                }
            }
        }
    }
}

// ============== fp16 tensor GEMM for recurrence: M=128, BN=64, BK=32 =======
// C[128,N] = A[128,512]h * B[N,512]h^T ; 8 warps (4m x 2n), warp tile 32x32
// mode: 1 +bias f32 out ; 2 +bias +Add f32 out
__global__ __launch_bounds__(256) void hgemm_s(
    const __half* __restrict__ A,
    const __half* __restrict__ B, int ldb,
    float* __restrict__ C, int ldc,
    const float* __restrict__ bias,
    const float* __restrict__ Add, int ldadd, int mode)
{
    __shared__ __half As[2][128][40];
    __shared__ __half Bs[2][64][40];
    int tid = threadIdx.x, lane = tid & 31, warp = tid >> 5;
    int wm = warp >> 1, wn = warp & 1;
    int bn = blockIdx.x;

    int ar = tid >> 1, ac = (tid & 1) * 16;
    int br = tid >> 2, bc = (tid & 3) * 8;
    const __half* Ap = A + (size_t)ar * 512 + ac;
    const __half* Bp = B + (size_t)(bn * 64 + br) * ldb + bc;

    float acc[2][4][4] = {};
    int a_r = ((lane >> 3) & 1) * 8 + (lane & 7);
    int a_c = (lane >> 4) * 8;
    int b_r = ((lane >> 4) & 1) * 8 + (lane & 7);
    int b_c = ((lane >> 3) & 1) * 8;

    uint4 av0 = *(const uint4*)(Ap);
    uint4 av1 = *(const uint4*)(Ap + 8);
    uint4 bv  = *(const uint4*)(Bp);
    *(uint4*)&As[0][ar][ac] = av0; *(uint4*)&As[0][ar][ac + 8] = av1;
    *(uint4*)&Bs[0][br][bc] = bv;
    __syncthreads();

    int cur = 0;
#pragma unroll 4
    for (int kt = 0; kt < 16; ++kt) {
        if (kt < 15) {
            av0 = *(const uint4*)(Ap + (kt + 1) * 32);
            av1 = *(const uint4*)(Ap + (kt + 1) * 32 + 8);
            bv  = *(const uint4*)(Bp + (kt + 1) * 32);
        }
        uint32_t asb = (uint32_t)__cvta_generic_to_shared(&As[cur][0][0]);
        uint32_t bsb = (uint32_t)__cvta_generic_to_shared(&Bs[cur][0][0]);
#pragma unroll
        for (int ks = 0; ks < 2; ++ks) {
            int k = ks * 16;
            uint32_t af[2][4], bf[4][2];
#pragma unroll
            for (int mi = 0; mi < 2; ++mi) {
                uint32_t addr = asb +
                    (uint32_t)(((wm * 32 + mi * 16 + a_r) * 40 + k + a_c) * 2);
                ldsm4(af[mi], addr);
            }
#pragma unroll
            for (int nh = 0; nh < 2; ++nh) {
                uint32_t r[4];
                uint32_t addr = bsb +
                    (uint32_t)(((wn * 32 + nh * 16 + b_r) * 40 + k + b_c) * 2);
                ldsm4(r, addr);
                bf[2 * nh + 0][0] = r[0]; bf[2 * nh + 0][1] = r[1];
                bf[2 * nh + 1][0] = r[2]; bf[2 * nh + 1][1] = r[3];
            }
#pragma unroll
            for (int mi = 0; mi < 2; ++mi)
#pragma unroll
                for (int ni = 0; ni < 4; ++ni)
                    mma16816(acc[mi][ni], af[mi], bf[ni]);
        }
        if (kt < 15) {
            __syncthreads();
            cur ^= 1;
            *(uint4*)&As[cur][ar][ac] = av0; *(uint4*)&As[cur][ar][ac + 8] = av1;
            *(uint4*)&Bs[cur][br][bc] = bv;
            __syncthreads();
        }
    }

    int mb = wm * 32;
    int nb = bn * 64 + wn * 32;
    int qr = lane >> 2, qc = (lane & 3) * 2;
#pragma unroll
    for (int mi = 0; mi < 2; ++mi) {
#pragma unroll
        for (int ni = 0; ni < 4; ++ni) {
            int n = nb + ni * 8 + qc;
            float bv0 = bias[n], bv1 = bias[n + 1];
            float* c4 = acc[mi][ni];
#pragma unroll
            for (int half_ = 0; half_ < 2; ++half_) {
                int m = mb + mi * 16 + qr + half_ * 8;
                float v0 = c4[half_ * 2 + 0] + bv0;
                float v1 = c4[half_ * 2 + 1] + bv1;
                if (mode == 2) {
                    v0 += Add[(size_t)m * ldadd + n];
                    v1 += Add[(size_t)m * ldadd + n + 1];
                }
                *(float2*)&C[(size_t)m * ldc + n] = make_float2(v0, v1);
            }
        }
    }
}

// ---------------- fp32 NT SGEMM (prologue W' only) -------------------------
__global__ __launch_bounds__(256) void sgemm_nt_big(
    const float* __restrict__ A, int lda,
    const float* __restrict__ B, int ldb,
    float* __restrict__ C, int ldc, int K)
{
    __shared__ float As[8][128];
    __shared__ float Bs[8][128];
    int tid = threadIdx.x;
    int bn = blockIdx.x, bm = blockIdx.y;
    int ldrow = tid >> 1;
    int ldk   = (tid & 1) * 4;
    const float* Ap = A + (size_t)(bm * 128 + ldrow) * lda + ldk;
    const float* Bp = B + (size_t)(bn * 128 + ldrow) * ldb + ldk;
    int tx = tid & 15, ty = tid >> 4;
    float acc[8][8] = {};

    for (int k0 = 0; k0 < K; k0 += 8) {
        float4 a4 = *(const float4*)(Ap + k0);
        float4 b4 = *(const float4*)(Bp + k0);
        As[ldk + 0][ldrow] = a4.x; As[ldk + 1][ldrow] = a4.y;
        As[ldk + 2][ldrow] = a4.z; As[ldk + 3][ldrow] = a4.w;
        Bs[ldk + 0][ldrow] = b4.x; Bs[ldk + 1][ldrow] = b4.y;
        Bs[ldk + 2][ldrow] = b4.z; Bs[ldk + 3][ldrow] = b4.w;
        __syncthreads();
#pragma unroll
        for (int k = 0; k < 8; ++k) {
            float ra[8], rb[8];
#pragma unroll
            for (int i = 0; i < 8; ++i) ra[i] = As[k][ty * 8 + i];
#pragma unroll
            for (int j = 0; j < 8; ++j) rb[j] = Bs[k][tx * 8 + j];
#pragma unroll
            for (int i = 0; i < 8; ++i)
#pragma unroll
                for (int j = 0; j < 8; ++j)
                    acc[i][j] += ra[i] * rb[j];
        }
        __syncthreads();
    }
    int mbase = bm * 128 + ty * 8;
    int nbase = bn * 128 + tx * 8;
#pragma unroll
    for (int i = 0; i < 8; ++i)
#pragma unroll
        for (int j = 0; j < 8; ++j)
            C[(size_t)(mbase + i) * ldc + nbase + j] = acc[i][j];
}

// -------- embedding gather -> fp16 -----------------------------------------
__global__ void gather_embed_h(const int* __restrict__ captions,
                               const float* __restrict__ emb,
                               __half* __restrict__ xe)
{
    int m = blockIdx.x;            // m = t*128 + b
    int t = m >> 7, b = m & 127;
    int cap = captions[b * TCAP + t];
    float4 v = ((const float4*)(emb + (size_t)cap * E_))[threadIdx.x];
    __half2* dst = (__half2*)(xe + (size_t)m * E_);
    dst[2 * threadIdx.x + 0] = __floats2half2_rn(v.x, v.y);
    dst[2 * threadIdx.x + 1] = __floats2half2_rn(v.z, v.w);
}

// -------- generic f32 -> f16 (n % 4 == 0) -----------------------------------
__global__ void f2h(const float* __restrict__ in, __half* __restrict__ out, int n)
{
    int i = (blockIdx.x * blockDim.x + threadIdx.x) * 4;
    if (i < n) {
        float4 v = *(const float4*)(in + i);
        ((__half2*)(out + i))[0] = __floats2half2_rn(v.x, v.y);
        ((__half2*)(out + i))[1] = __floats2half2_rn(v.z, v.w);
    }
}

// -------- gru_wih[:, :512] -> fp16 compact ----------------------------------
__global__ void conv_wihx(const float* __restrict__ wih, __half* __restrict__ out)
{
    int n = blockIdx.x;            // 0..1535
    int t = threadIdx.x;           // 0..127
    float4 v = *(const float4*)(wih + (size_t)n * 1024 + t * 4);
    __half2* o = (__half2*)(out + (size_t)n * 512 + t * 4);
    o[0] = __floats2half2_rn(v.x, v.y);
    o[1] = __floats2half2_rn(v.z, v.w);
}

// -------- 512x512 transpose --------------------------------------------------
__global__ void transpose512(const float* __restrict__ in, float* __restrict__ out)
{
    __shared__ float tile[32][33];
    int x = blockIdx.x * 32 + threadIdx.x;
    int y = blockIdx.y * 32 + threadIdx.y;
#pragma unroll
    for (int j = 0; j < 4; ++j)
        tile[threadIdx.y + 8 * j][threadIdx.x] = in[(size_t)(y + 8 * j) * 512 + x];
    __syncthreads();
    int x2 = blockIdx.y * 32 + threadIdx.x;
    int y2 = blockIdx.x * 32 + threadIdx.y;
#pragma unroll
    for (int j = 0; j < 4; ++j)
        out[(size_t)(y2 + 8 * j) * 512 + x2] = tile[threadIdx.x][threadIdx.y + 8 * j];
}

// -------- bias2 = Wih_ctx @ fc0_b + b_ih ------------------------------------
__global__ void bias2_kernel(const float* __restrict__ wih, const float* __restrict__ fc0b,
                             const float* __restrict__ bih, float* __restrict__ out)
{
    int n = blockIdx.x * blockDim.x + threadIdx.x;
    if (n < 1536) {
        float s = 0.f;
        for (int j = 0; j < 512; ++j) s += wih[(size_t)n * 1024 + 512 + j] * fc0b[j];
        out[n] = s + bih[n];
    }
}

__global__ void bcat_kernel(const float* __restrict__ bhh, float* __restrict__ out)
{
    int j = blockIdx.x * blockDim.x + threadIdx.x;
    if (j < 2048) out[j] = (j < 512) ? 0.f : bhh[j - 512];
}

// -------- fused Bahdanau attention (fp16 keys/features, fp16 ctx out) -------
__global__ __launch_bounds__(256) void attention_kernel(
    const float* __restrict__ qgh,       // (B, 2048): q is cols [0,512)
    const __half* __restrict__ keys,     // (B,S,H) fp16
    const float* __restrict__ att_v,     // (H)
    const __half* __restrict__ features, // (B,S,K) fp16
    __half* __restrict__ ctx)            // (B,K) fp16
{
    __shared__ float qs[H_];
    __shared__ float av[H_];
    __shared__ float sc[S_];
    __shared__ float red[8];

    int b = blockIdx.x, tid = threadIdx.x;
    for (int i = tid; i < H_; i += 256) { qs[i] = qgh[b * 2048 + i]; av[i] = att_v[i]; }
    __syncthreads();

    int warp = tid >> 5, lane = tid & 31;
    const __half2* kpb = (const __half2*)(keys + (size_t)b * S_ * H_);
    for (int s = warp; s < S_; s += 8) {
        const __half2* kps = kpb + (size_t)s * (H_ / 2);
        float acc = 0.f;
        for (int i = lane; i < H_ / 2; i += 32) {
            float2 kv = __half22float2(kps[i]);
            acc += av[2 * i]     * tanhf(qs[2 * i]     + kv.x)
                 + av[2 * i + 1] * tanhf(qs[2 * i + 1] + kv.y);
        }
#pragma unroll
        for (int o = 16; o; o >>= 1) acc += __shfl_xor_sync(~0u, acc, o);
        if (!lane) sc[s] = acc;
    }
    __syncthreads();

    float m = -INFINITY;
    for (int s = tid; s < S_; s += 256) m = fmaxf(m, sc[s]);
#pragma unroll
    for (int o = 16; o; o >>= 1) m = fmaxf(m, __shfl_xor_sync(~0u, m, o));
    if (!lane) red[warp] = m;
    __syncthreads();
    m = red[0];
#pragma unroll
    for (int w = 1; w < 8; ++w) m = fmaxf(m, red[w]);
    __syncthreads();

    float ls = 0.f;
    for (int s = tid; s < S_; s += 256) { float e = expf(sc[s] - m); sc[s] = e; ls += e; }
#pragma unroll
    for (int o = 16; o; o >>= 1) ls += __shfl_xor_sync(~0u, ls, o);
    if (!lane) red[warp] = ls;
    __syncthreads();
    float sum = 0.f;
#pragma unroll
    for (int w = 0; w < 8; ++w) sum += red[w];
    float inv = 1.f / sum;

    const __half* fb = features + (size_t)b * S_ * K_;
    for (int k = tid; k < K_; k += 256) {
        float acc = 0.f;
        for (int s = 0; s < S_; ++s)
            acc += sc[s] * __half2float(fb[(size_t)s * K_ + k]);
        ctx[b * K_ + k] = __float2half(acc * inv);
    }
}

// -------- GRU gates (writes fp32 master + fp16 copy) ------------------------
__global__ void gru_gate(const float* __restrict__ gi, const float* __restrict__ qgh,
                         const float* __restrict__ hprev, float* __restrict__ hnew,
                         __half* __restrict__ hnew16)
{
    int idx = blockIdx.x * blockDim.x + threadIdx.x;   // 0..65535
    int b = idx >> 9, j = idx & 511;
    const float* ghb = qgh + (size_t)b * 2048 + 512;
    int base = b * 1536 + j;
    float ir = gi[base], iz = gi[base + 512], in_ = gi[base + 1024];
    float hr = ghb[j], hz = ghb[512 + j], hn = ghb[1024 + j];
    float r = 1.f / (1.f + expf(-(ir + hr)));
    float z = 1.f / (1.f + expf(-(iz + hz)));
    float n = tanhf(in_ + r * hn);
    float v = (1.f - z) * n + z * hprev[idx];
    hnew[idx] = v;
    hnew16[idx] = __float2half(v);
}

__global__ void zero_kernel(float* p, int n)
{
    int idx = blockIdx.x * blockDim.x + threadIdx.x;
    if (idx < n) p[idx] = 0.f;
}

// ---------------- launch -----------------------------------------------------
extern "C" void kernel_launch(void* const* d_in, const int* in_sizes, int n_in,
                              void* d_out, int out_size)
{
    const float* features = (const float*)d_in[0];
    const int*   captions = (const int*)  d_in[1];
    const float* emb      = (const float*)d_in[2];
    const float* fc1_w    = (const float*)d_in[3];
    const float* fc1_b    = (const float*)d_in[4];
    const float* att_wq   = (const float*)d_in[5];
    const float* att_wk   = (const float*)d_in[6];
    const float* att_v    = (const float*)d_in[7];
    const float* fc0_w    = (const float*)d_in[8];
    const float* fc0_b    = (const float*)d_in[9];
    const float* gru_wih  = (const float*)d_in[10];
    const float* gru_whh  = (const float*)d_in[11];
    const float* gru_bih  = (const float*)d_in[12];
    const float* gru_bhh  = (const float*)d_in[13];
    const float* fc2_w    = (const float*)d_in[14];
    const float* fc2_b    = (const float*)d_in[15];
    float* out = (float*)d_out;

    float *gix, *h, *qgh, *gi, *bcat, *wprime, *bias2, *fc0wT;
    __half *xe_h, *x_h, *fc1w_h, *wk_h, *feat_h, *keys_h, *wihx_h, *fc2w_h;
    __half *h16, *ctx_h, *wcat_h, *wprime_h;
    cudaGetSymbolAddress((void**)&gix,      g_gix);
    cudaGetSymbolAddress((void**)&h,        g_h);
    cudaGetSymbolAddress((void**)&qgh,      g_qgh);
    cudaGetSymbolAddress((void**)&gi,       g_gi);
    cudaGetSymbolAddress((void**)&bcat,     g_bcat);
    cudaGetSymbolAddress((void**)&wprime,   g_wprime);
    cudaGetSymbolAddress((void**)&bias2,    g_bias2);
    cudaGetSymbolAddress((void**)&fc0wT,    g_fc0wT);
    cudaGetSymbolAddress((void**)&xe_h,     g_xe_h);
    cudaGetSymbolAddress((void**)&x_h,      g_x_h);
    cudaGetSymbolAddress((void**)&fc1w_h,   g_fc1w_h);
    cudaGetSymbolAddress((void**)&wk_h,     g_wk_h);
    cudaGetSymbolAddress((void**)&feat_h,   g_feat_h);
    cudaGetSymbolAddress((void**)&keys_h,   g_keys_h);
    cudaGetSymbolAddress((void**)&wihx_h,   g_wihx_h);
    cudaGetSymbolAddress((void**)&fc2w_h,   g_fc2w_h);
    cudaGetSymbolAddress((void**)&h16,      g_h16);
    cudaGetSymbolAddress((void**)&ctx_h,    g_ctx_h);
    cudaGetSymbolAddress((void**)&wcat_h,   g_wcat_h);
    cudaGetSymbolAddress((void**)&wprime_h, g_wprime_h);

    // ---- launches 0..4: conversions feeding the keys GEMM ----
    gather_embed_h<<<TOUT * B_, 128>>>(captions, emb, xe_h);                 // 0
    f2h<<<(H_ * E_ / 4 + 255) / 256, 256>>>(fc1_w, fc1w_h, H_ * E_);         // 1
    f2h<<<(H_ * K_ / 4 + 255) / 256, 256>>>(att_wk, wk_h, H_ * K_);          // 2
    f2h<<<(B_ * S_ * K_ / 4 + 255) / 256, 256>>>(features, feat_h,
                                                 B_ * S_ * K_);              // 3
    f2h<<<(V_ * H_ / 4 + 255) / 256, 256>>>(fc2_w, fc2w_h, V_ * H_);         // 4

    // ---- launch 5 (ncu -s 5 profiles this): keys_proj fp16 GEMM ----
    // keys = features @ att_wk^T   (25088 x 512 x 512), fp16 out
    hgemm_nt<<<dim3(H_ / 128, B_ * S_ / 128), 256>>>(
        feat_h, K_, wk_h, K_, keys_h, H_, K_, nullptr, 5);                   // 5

    // ---- remaining prologue ----
    conv_wihx<<<1536, 128>>>(gru_wih, wihx_h);
    f2h<<<(512 * 512 / 4 + 255) / 256, 256>>>(att_wq, wcat_h, 512 * 512);
    f2h<<<(1536 * 512 / 4 + 255) / 256, 256>>>(gru_whh, wcat_h + 512 * 512,
                                               1536 * 512);
    transpose512<<<dim3(16, 16), dim3(32, 8)>>>(fc0_w, fc0wT);
    bias2_kernel<<<12, 128>>>(gru_wih, fc0_b, gru_bih, bias2);
    bcat_kernel<<<8, 256>>>(gru_bhh, bcat);

    // fc1: x_h = fp16(xe @ fc1_w^T + b)           (1920 x 512 x 512)
    hgemm_nt<<<dim3(H_ / 128, TOUT * B_ / 128), 256>>>(
        xe_h, E_, fc1w_h, E_, x_h, H_, E_, fc1_b, 4);
    // gix = x @ Wih_x^T (fp32 out)                (1920 x 1536 x 512)
    hgemm_nt<<<dim3(3 * H_ / 128, TOUT * B_ / 128), 256>>>(
        x_h, H_, wihx_h, H_, gix, 3 * H_, H_, nullptr, 0);
    // W' = Wih_ctx @ fc0_w  (fp32, via fc0_w^T)   (1536 x 512 x 512)
    sgemm_nt_big<<<dim3(4, 12), 256>>>(
        gru_wih + 512, 1024, fc0wT, 512, wprime, 512, 512);
    f2h<<<(1536 * 512 / 4 + 255) / 256, 256>>>(wprime, wprime_h, 1536 * 512);

    zero_kernel<<<(B_ * H_ + 1023) / 1024, 1024>>>(h, B_ * H_);
    zero_kernel<<<(B_ * H_ / 2 + 1023) / 1024, 1024>>>((float*)h16, B_ * H_ / 2);

    // ---- recurrence ----
    for (int t = 0; t < TOUT; ++t) {
        const __half* h16prev = h16 + (size_t)t * B_ * H_;
        float*        hprev   = h   + (size_t)t * B_ * H_;
        float*        hnew    = h   + (size_t)(t + 1) * B_ * H_;
        __half*       h16new  = h16 + (size_t)(t + 1) * B_ * H_;

        // [q | gh] = h @ [Wq ; Whh]^T + [0 ; bhh]   (128 x 2048 x 512)
        hgemm_s<<<2048 / 64, 256>>>(
            h16prev, wcat_h, 512, qgh, 2048, bcat, nullptr, 0, 1);

        attention_kernel<<<B_, 256>>>(qgh, keys_h, att_v, feat_h, ctx_h);

        // gi = ctx @ W'^T + bias2 + gix_t           (128 x 1536 x 512)
        hgemm_s<<<1536 / 64, 256>>>(
            ctx_h, wprime_h, 512, gi, 1536,
            bias2, gix + (size_t)t * B_ * 3 * H_, 1536, 2);

        gru_gate<<<B_ * H_ / 1024, 1024>>>(gi, qgh, hprev, hnew, h16new);
    }

    // ---- logits: fp16 tensor GEMM (1920 x 32000 x 512), remap + bias ----
    hgemm_nt<<<dim3(V_ / 128, TOUT * B_ / 128), 256>>>(
        h16 + B_ * H_, H_, fc2w_h, H_, out, V_, H_, fc2_b, 3);
}

// round 5
// speedup vs baseline: 6.9678x; 1.2327x over previous
#include <cuda_runtime.h>
#include <cuda_fp16.h>
#include <cuda_bf16.h>
#include <math.h>
#include <stdint.h>

// Problem dims
#define B_   128
#define S_   196
#define K_   512
#define TCAP 16
#define TOUT 15
#define V_   32000
#define E_   512
#define H_   512

// ---------------- scratch (device globals; allocation-free) ----------------
__device__ float g_gix[TOUT * B_ * 3 * H_];        // x_t @ Wx^T  (t*128+b, 1536)
__device__ float g_h[(TOUT + 1) * B_ * H_];        // h_0..h_15 fp32 master
__device__ float g_qgh[B_ * 2048];                 // per-step [q | gh]
__device__ float g_gi[B_ * 3 * H_];
__device__ float g_bcat[2048];                     // [0 ; gru_bhh]
__device__ float g_bias2[1536];                    // Wih_ctx@fc0_b + b_ih
__device__ float g_fc0wT[512 * 512];

// fp16 operands
__device__ __half g_xe_h[TOUT * B_ * E_];
__device__ __half g_x_h[TOUT * B_ * H_];
__device__ __half g_fc1w_h[H_ * E_];
__device__ __half g_wk_h[H_ * K_];
__device__ __half g_feat_h[(size_t)B_ * S_ * K_];
__device__ __half g_keys_h[(size_t)B_ * S_ * H_];
__device__ __half g_wihx_h[1536 * 512];
__device__ __half g_wihc_h[1536 * 512];
__device__ __half g_fc0wT_h[512 * 512];
__device__ __half g_fc2w_h[(size_t)V_ * H_];
__device__ __half g_h16[(TOUT + 1) * B_ * H_];     // fp16 h, slot 0 = zeros
__device__ __half g_ctx_h[B_ * K_];
__device__ __half g_wcat_h[2048 * 512];            // [att_wq ; gru_whh] fp16
__device__ __half g_wprime_h[1536 * 512];

// ---------------- fast math helpers ----------------------------------------
__device__ __forceinline__ float tanh_fast(float x) {
    float y;
    asm("tanh.approx.f32 %0, %1;" : "=f"(y) : "f"(x));
    return y;
}

// ========================= mma helpers =====================================
__device__ __forceinline__ void ldsm4(uint32_t* r, uint32_t addr) {
    asm volatile("ldmatrix.sync.aligned.m8n8.x4.shared.b16 {%0,%1,%2,%3}, [%4];"
        : "=r"(r[0]), "=r"(r[1]), "=r"(r[2]), "=r"(r[3]) : "r"(addr));
}
__device__ __forceinline__ void mma16816(float* c, const uint32_t* a, const uint32_t* b) {
    asm volatile("mma.sync.aligned.m16n8k16.row.col.f32.f16.f16.f32 "
        "{%0,%1,%2,%3}, {%4,%5,%6,%7}, {%8,%9}, {%0,%1,%2,%3};"
        : "+f"(c[0]), "+f"(c[1]), "+f"(c[2]), "+f"(c[3])
        : "r"(a[0]), "r"(a[1]), "r"(a[2]), "r"(a[3]), "r"(b[0]), "r"(b[1]));
}

// ========================= fp16 tensor-core NT GEMM (big) ==================
// C[M,N] = A[M,K]h * B[N,K]h^T ; BM=BN=128, BK=32, 256 thr, 8 warps (2m x 4n)
// modes: 0 plain f32, 3 +bias remap (m=t*128+b -> row b*15+t),
//        4 +bias store fp16, 5 plain store fp16
__global__ __launch_bounds__(256) void hgemm_nt(
    const __half* __restrict__ A, int lda,
    const __half* __restrict__ B, int ldb,
    void* __restrict__ Cv, int ldc, int K,
    const float* __restrict__ bias, int mode)
{
    __shared__ __half As[2][128][40];
    __shared__ __half Bs[2][128][40];
    int tid = threadIdx.x, lane = tid & 31, warp = tid >> 5;
    int wm = warp & 1, wn = warp >> 1;
    int bn = blockIdx.x, bm = blockIdx.y;

    int r0 = tid >> 2, r1 = r0 + 64;
    int kc = (tid & 3) * 8;
    const __half* Ap0 = A + (size_t)(bm * 128 + r0) * lda + kc;
    const __half* Ap1 = A + (size_t)(bm * 128 + r1) * lda + kc;
    const __half* Bp0 = B + (size_t)(bn * 128 + r0) * ldb + kc;
    const __half* Bp1 = B + (size_t)(bn * 128 + r1) * ldb + kc;

    float acc[4][4][4] = {};
    int a_r = ((lane >> 3) & 1) * 8 + (lane & 7);
    int a_c = (lane >> 4) * 8;
    int b_r = ((lane >> 4) & 1) * 8 + (lane & 7);
    int b_c = ((lane >> 3) & 1) * 8;

    uint4 av0 = *(const uint4*)(Ap0);
    uint4 av1 = *(const uint4*)(Ap1);
    uint4 bv0 = *(const uint4*)(Bp0);
    uint4 bv1 = *(const uint4*)(Bp1);
    *(uint4*)&As[0][r0][kc] = av0; *(uint4*)&As[0][r1][kc] = av1;
    *(uint4*)&Bs[0][r0][kc] = bv0; *(uint4*)&Bs[0][r1][kc] = bv1;
    __syncthreads();

    int nkt = K / 32, cur = 0;
    for (int kt = 0; kt < nkt; ++kt) {
        if (kt + 1 < nkt) {
            av0 = *(const uint4*)(Ap0 + (kt + 1) * 32);
            av1 = *(const uint4*)(Ap1 + (kt + 1) * 32);
            bv0 = *(const uint4*)(Bp0 + (kt + 1) * 32);
            bv1 = *(const uint4*)(Bp1 + (kt + 1) * 32);
        }
        uint32_t as_base = (uint32_t)__cvta_generic_to_shared(&As[cur][0][0]);
        uint32_t bs_base = (uint32_t)__cvta_generic_to_shared(&Bs[cur][0][0]);
#pragma unroll
        for (int ks = 0; ks < 2; ++ks) {
            int k = ks * 16;
            uint32_t af[4][4], bf[4][2];
#pragma unroll
            for (int mi = 0; mi < 4; ++mi) {
                uint32_t addr = as_base +
                    (uint32_t)(((wm * 64 + mi * 16 + a_r) * 40 + k + a_c) * 2);
                ldsm4(af[mi], addr);
            }
#pragma unroll
            for (int nh = 0; nh < 2; ++nh) {
                uint32_t r[4];
                uint32_t addr = bs_base +
                    (uint32_t)(((wn * 32 + nh * 16 + b_r) * 40 + k + b_c) * 2);
                ldsm4(r, addr);
                bf[2 * nh + 0][0] = r[0]; bf[2 * nh + 0][1] = r[1];
                bf[2 * nh + 1][0] = r[2]; bf[2 * nh + 1][1] = r[3];
            }
#pragma unroll
            for (int mi = 0; mi < 4; ++mi)
#pragma unroll
                for (int ni = 0; ni < 4; ++ni)
                    mma16816(acc[mi][ni], af[mi], bf[ni]);
        }
        if (kt + 1 < nkt) {
            __syncthreads();
            cur ^= 1;
            *(uint4*)&As[cur][r0][kc] = av0; *(uint4*)&As[cur][r1][kc] = av1;
            *(uint4*)&Bs[cur][r0][kc] = bv0; *(uint4*)&Bs[cur][r1][kc] = bv1;
            __syncthreads();
        }
    }

    int mb = bm * 128 + wm * 64;
    int nb = bn * 128 + wn * 32;
    int qr = lane >> 2, qc = (lane & 3) * 2;
#pragma unroll
    for (int mi = 0; mi < 4; ++mi) {
#pragma unroll
        for (int ni = 0; ni < 4; ++ni) {
            int n = nb + ni * 8 + qc;
            float bv = 0.f, bv2 = 0.f;
            if (mode == 3 || mode == 4) { bv = bias[n]; bv2 = bias[n + 1]; }
            float* c4 = acc[mi][ni];
#pragma unroll
            for (int half_ = 0; half_ < 2; ++half_) {
                int m = mb + mi * 16 + qr + half_ * 8;
                float v0 = c4[half_ * 2 + 0] + bv;
                float v1 = c4[half_ * 2 + 1] + bv2;
                if (mode == 4 || mode == 5) {
                    __half* C = (__half*)Cv;
                    *(__half2*)&C[(size_t)m * ldc + n] =
                        __halves2half2(__float2half(v0), __float2half(v1));
                } else if (mode == 3) {
                    int b = m & 127, t = m >> 7;
                    float* C = (float*)Cv;
                    *(float2*)&C[((size_t)b * TOUT + t) * ldc + n] = make_float2(v0, v1);
                } else {
                    float* C = (float*)Cv;
                    *(float2*)&C[(size_t)m * ldc + n] = make_float2(v0, v1);
                }
            }
        }
    }
}

// ============== fp16 tensor GEMM for recurrence: M=128, BN=64, BK=32 =======
// mode: 1 +bias f32 out ; 2 +bias +Add f32 out
__global__ __launch_bounds__(256) void hgemm_s(
    const __half* __restrict__ A,
    const __half* __restrict__ B, int ldb,
    float* __restrict__ C, int ldc,
    const float* __restrict__ bias,
    const float* __restrict__ Add, int ldadd, int mode)
{
    __shared__ __half As[2][128][40];
    __shared__ __half Bs[2][64][40];
    int tid = threadIdx.x, lane = tid & 31, warp = tid >> 5;
    int wm = warp >> 1, wn = warp & 1;
    int bn = blockIdx.x;

    int ar = tid >> 1, ac = (tid & 1) * 16;
    int br = tid >> 2, bc = (tid & 3) * 8;
    const __half* Ap = A + (size_t)ar * 512 + ac;
    const __half* Bp = B + (size_t)(bn * 64 + br) * ldb + bc;

    float acc[2][4][4] = {};
    int a_r = ((lane >> 3) & 1) * 8 + (lane & 7);
    int a_c = (lane >> 4) * 8;
    int b_r = ((lane >> 4) & 1) * 8 + (lane & 7);
    int b_c = ((lane >> 3) & 1) * 8;

    uint4 av0 = *(const uint4*)(Ap);
    uint4 av1 = *(const uint4*)(Ap + 8);
    uint4 bv  = *(const uint4*)(Bp);
    *(uint4*)&As[0][ar][ac] = av0; *(uint4*)&As[0][ar][ac + 8] = av1;
    *(uint4*)&Bs[0][br][bc] = bv;
    __syncthreads();

    int cur = 0;
#pragma unroll 4
    for (int kt = 0; kt < 16; ++kt) {
        if (kt < 15) {
            av0 = *(const uint4*)(Ap + (kt + 1) * 32);
            av1 = *(const uint4*)(Ap + (kt + 1) * 32 + 8);
            bv  = *(const uint4*)(Bp + (kt + 1) * 32);
        }
        uint32_t asb = (uint32_t)__cvta_generic_to_shared(&As[cur][0][0]);
        uint32_t bsb = (uint32_t)__cvta_generic_to_shared(&Bs[cur][0][0]);
#pragma unroll
        for (int ks = 0; ks < 2; ++ks) {
            int k = ks * 16;
            uint32_t af[2][4], bf[4][2];
#pragma unroll
            for (int mi = 0; mi < 2; ++mi) {
                uint32_t addr = asb +
                    (uint32_t)(((wm * 32 + mi * 16 + a_r) * 40 + k + a_c) * 2);
                ldsm4(af[mi], addr);
            }
#pragma unroll
            for (int nh = 0; nh < 2; ++nh) {
                uint32_t r[4];
                uint32_t addr = bsb +
                    (uint32_t)(((wn * 32 + nh * 16 + b_r) * 40 + k + b_c) * 2);
                ldsm4(r, addr);
                bf[2 * nh + 0][0] = r[0]; bf[2 * nh + 0][1] = r[1];
                bf[2 * nh + 1][0] = r[2]; bf[2 * nh + 1][1] = r[3];
            }
#pragma unroll
            for (int mi = 0; mi < 2; ++mi)
#pragma unroll
                for (int ni = 0; ni < 4; ++ni)
                    mma16816(acc[mi][ni], af[mi], bf[ni]);
        }
        if (kt < 15) {
            __syncthreads();
            cur ^= 1;
            *(uint4*)&As[cur][ar][ac] = av0; *(uint4*)&As[cur][ar][ac + 8] = av1;
            *(uint4*)&Bs[cur][br][bc] = bv;
            __syncthreads();
        }
    }

    int mb = wm * 32;
    int nb = bn * 64 + wn * 32;
    int qr = lane >> 2, qc = (lane & 3) * 2;
#pragma unroll
    for (int mi = 0; mi < 2; ++mi) {
#pragma unroll
        for (int ni = 0; ni < 4; ++ni) {
            int n = nb + ni * 8 + qc;
            float bv0 = bias[n], bv1 = bias[n + 1];
            float* c4 = acc[mi][ni];
#pragma unroll
            for (int half_ = 0; half_ < 2; ++half_) {
                int m = mb + mi * 16 + qr + half_ * 8;
                float v0 = c4[half_ * 2 + 0] + bv0;
                float v1 = c4[half_ * 2 + 1] + bv1;
                if (mode == 2) {
                    v0 += Add[(size_t)m * ldadd + n];
                    v1 += Add[(size_t)m * ldadd + n + 1];
                }
                *(float2*)&C[(size_t)m * ldc + n] = make_float2(v0, v1);
            }
        }
    }
}

// -------- embedding gather -> fp16 -----------------------------------------
__global__ void gather_embed_h(const int* __restrict__ captions,
                               const float* __restrict__ emb,
                               __half* __restrict__ xe)
{
    int m = blockIdx.x;            // m = t*128 + b
    int t = m >> 7, b = m & 127;
    int cap = captions[b * TCAP + t];
    float4 v = ((const float4*)(emb + (size_t)cap * E_))[threadIdx.x];
    __half2* dst = (__half2*)(xe + (size_t)m * E_);
    dst[2 * threadIdx.x + 0] = __floats2half2_rn(v.x, v.y);
    dst[2 * threadIdx.x + 1] = __floats2half2_rn(v.z, v.w);
}

// -------- generic f32 -> f16 (n % 4 == 0) -----------------------------------
__global__ void f2h(const float* __restrict__ in, __half* __restrict__ out, int n)
{
    int i = (blockIdx.x * blockDim.x + threadIdx.x) * 4;
    if (i < n) {
        float4 v = *(const float4*)(in + i);
        ((__half2*)(out + i))[0] = __floats2half2_rn(v.x, v.y);
        ((__half2*)(out + i))[1] = __floats2half2_rn(v.z, v.w);
    }
}

// -------- gru_wih column-slice -> fp16 compact (offset 0 or 512) ------------
__global__ void conv_wih_part(const float* __restrict__ wih, __half* __restrict__ out,
                              int off)
{
    int n = blockIdx.x;            // 0..1535
    int t = threadIdx.x;           // 0..127
    float4 v = *(const float4*)(wih + (size_t)n * 1024 + off + t * 4);
    __half2* o = (__half2*)(out + (size_t)n * 512 + t * 4);
    o[0] = __floats2half2_rn(v.x, v.y);
    o[1] = __floats2half2_rn(v.z, v.w);
}

// -------- 512x512 transpose --------------------------------------------------
__global__ void transpose512(const float* __restrict__ in, float* __restrict__ out)
{
    __shared__ float tile[32][33];
    int x = blockIdx.x * 32 + threadIdx.x;
    int y = blockIdx.y * 32 + threadIdx.y;
#pragma unroll
    for (int j = 0; j < 4; ++j)
        tile[threadIdx.y + 8 * j][threadIdx.x] = in[(size_t)(y + 8 * j) * 512 + x];
    __syncthreads();
    int x2 = blockIdx.y * 32 + threadIdx.x;
    int y2 = blockIdx.x * 32 + threadIdx.y;
#pragma unroll
    for (int j = 0; j < 4; ++j)
        out[(size_t)(y2 + 8 * j) * 512 + x2] = tile[threadIdx.x][threadIdx.y + 8 * j];
}

// -------- bias2 = Wih_ctx @ fc0_b + b_ih ------------------------------------
__global__ void bias2_kernel(const float* __restrict__ wih, const float* __restrict__ fc0b,
                             const float* __restrict__ bih, float* __restrict__ out)
{
    int n = blockIdx.x * blockDim.x + threadIdx.x;
    if (n < 1536) {
        float s = 0.f;
        for (int j = 0; j < 512; ++j) s += wih[(size_t)n * 1024 + 512 + j] * fc0b[j];
        out[n] = s + bih[n];
    }
}

__global__ void bcat_kernel(const float* __restrict__ bhh, float* __restrict__ out)
{
    int j = blockIdx.x * blockDim.x + threadIdx.x;
    if (j < 2048) out[j] = (j < 512) ? 0.f : bhh[j - 512];
}

// -------- fused Bahdanau attention (fp16 keys/features, fp16 ctx out) -------
__global__ __launch_bounds__(256) void attention_kernel(
    const float* __restrict__ qgh,       // (B, 2048): q is cols [0,512)
    const __half* __restrict__ keys,     // (B,S,H) fp16
    const float* __restrict__ att_v,     // (H)
    const __half* __restrict__ features, // (B,S,K) fp16
    __half* __restrict__ ctx)            // (B,K) fp16
{
    __shared__ float qs[H_];
    __shared__ float av[H_];
    __shared__ float sc[S_];
    __shared__ float red[8];

    int b = blockIdx.x, tid = threadIdx.x;
    for (int i = tid; i < H_; i += 256) { qs[i] = qgh[b * 2048 + i]; av[i] = att_v[i]; }
    __syncthreads();

    int warp = tid >> 5, lane = tid & 31;
    const __half2* kpb = (const __half2*)(keys + (size_t)b * S_ * H_);
    for (int s = warp; s < S_; s += 8) {
        const __half2* kps = kpb + (size_t)s * (H_ / 2);
        float acc = 0.f;
        for (int i = lane; i < H_ / 2; i += 32) {
            float2 kv = __half22float2(kps[i]);
            acc += av[2 * i]     * tanh_fast(qs[2 * i]     + kv.x)
                 + av[2 * i + 1] * tanh_fast(qs[2 * i + 1] + kv.y);
        }
#pragma unroll
        for (int o = 16; o; o >>= 1) acc += __shfl_xor_sync(~0u, acc, o);
        if (!lane) sc[s] = acc;
    }
    __syncthreads();

    float m = -INFINITY;
    for (int s = tid; s < S_; s += 256) m = fmaxf(m, sc[s]);
#pragma unroll
    for (int o = 16; o; o >>= 1) m = fmaxf(m, __shfl_xor_sync(~0u, m, o));
    if (!lane) red[warp] = m;
    __syncthreads();
    m = red[0];
#pragma unroll
    for (int w = 1; w < 8; ++w) m = fmaxf(m, red[w]);
    __syncthreads();

    float ls = 0.f;
    for (int s = tid; s < S_; s += 256) { float e = __expf(sc[s] - m); sc[s] = e; ls += e; }
#pragma unroll
    for (int o = 16; o; o >>= 1) ls += __shfl_xor_sync(~0u, ls, o);
    if (!lane) red[warp] = ls;
    __syncthreads();
    float sum = 0.f;
#pragma unroll
    for (int w = 0; w < 8; ++w) sum += red[w];
    float inv = 1.f / sum;

    const __half* fb = features + (size_t)b * S_ * K_;
    for (int k = tid; k < K_; k += 256) {
        float acc = 0.f;
        for (int s = 0; s < S_; ++s)
            acc += sc[s] * __half2float(fb[(size_t)s * K_ + k]);
        ctx[b * K_ + k] = __float2half(acc * inv);
    }
}

// -------- GRU gates (writes fp32 master + fp16 copy) ------------------------
__global__ void gru_gate(const float* __restrict__ gi, const float* __restrict__ qgh,
                         const float* __restrict__ hprev, float* __restrict__ hnew,
                         __half* __restrict__ hnew16)
{
    int idx = blockIdx.x * blockDim.x + threadIdx.x;   // 0..65535
    int b = idx >> 9, j = idx & 511;
    const float* ghb = qgh + (size_t)b * 2048 + 512;
    int base = b * 1536 + j;
    float ir = gi[base], iz = gi[base + 512], in_ = gi[base + 1024];
    float hr = ghb[j], hz = ghb[512 + j], hn = ghb[1024 + j];
    float r = 1.f / (1.f + __expf(-(ir + hr)));
    float z = 1.f / (1.f + __expf(-(iz + hz)));
    float n = tanh_fast(in_ + r * hn);
    float v = (1.f - z) * n + z * hprev[idx];
    hnew[idx] = v;
    hnew16[idx] = __float2half(v);
}

__global__ void zero_kernel(float* p, int n)
{
    int idx = blockIdx.x * blockDim.x + threadIdx.x;
    if (idx < n) p[idx] = 0.f;
}

// ---------------- launch -----------------------------------------------------
extern "C" void kernel_launch(void* const* d_in, const int* in_sizes, int n_in,
                              void* d_out, int out_size)
{
    const float* features = (const float*)d_in[0];
    const int*   captions = (const int*)  d_in[1];
    const float* emb      = (const float*)d_in[2];
    const float* fc1_w    = (const float*)d_in[3];
    const float* fc1_b    = (const float*)d_in[4];
    const float* att_wq   = (const float*)d_in[5];
    const float* att_wk   = (const float*)d_in[6];
    const float* att_v    = (const float*)d_in[7];
    const float* fc0_w    = (const float*)d_in[8];
    const float* fc0_b    = (const float*)d_in[9];
    const float* gru_wih  = (const float*)d_in[10];
    const float* gru_whh  = (const float*)d_in[11];
    const float* gru_bih  = (const float*)d_in[12];
    const float* gru_bhh  = (const float*)d_in[13];
    const float* fc2_w    = (const float*)d_in[14];
    const float* fc2_b    = (const float*)d_in[15];
    float* out = (float*)d_out;

    float *gix, *h, *qgh, *gi, *bcat, *bias2, *fc0wT;
    __half *xe_h, *x_h, *fc1w_h, *wk_h, *feat_h, *keys_h, *wihx_h, *wihc_h;
    __half *fc0wT_h, *fc2w_h, *h16, *ctx_h, *wcat_h, *wprime_h;
    cudaGetSymbolAddress((void**)&gix,      g_gix);
    cudaGetSymbolAddress((void**)&h,        g_h);
    cudaGetSymbolAddress((void**)&qgh,      g_qgh);
    cudaGetSymbolAddress((void**)&gi,       g_gi);
    cudaGetSymbolAddress((void**)&bcat,     g_bcat);
    cudaGetSymbolAddress((void**)&bias2,    g_bias2);
    cudaGetSymbolAddress((void**)&fc0wT,    g_fc0wT);
    cudaGetSymbolAddress((void**)&xe_h,     g_xe_h);
    cudaGetSymbolAddress((void**)&x_h,      g_x_h);
    cudaGetSymbolAddress((void**)&fc1w_h,   g_fc1w_h);
    cudaGetSymbolAddress((void**)&wk_h,     g_wk_h);
    cudaGetSymbolAddress((void**)&feat_h,   g_feat_h);
    cudaGetSymbolAddress((void**)&keys_h,   g_keys_h);
    cudaGetSymbolAddress((void**)&wihx_h,   g_wihx_h);
    cudaGetSymbolAddress((void**)&wihc_h,   g_wihc_h);
    cudaGetSymbolAddress((void**)&fc0wT_h,  g_fc0wT_h);
    cudaGetSymbolAddress((void**)&fc2w_h,   g_fc2w_h);
    cudaGetSymbolAddress((void**)&h16,      g_h16);
    cudaGetSymbolAddress((void**)&ctx_h,    g_ctx_h);
    cudaGetSymbolAddress((void**)&wcat_h,   g_wcat_h);
    cudaGetSymbolAddress((void**)&wprime_h, g_wprime_h);

    // ---- conversions ----
    gather_embed_h<<<TOUT * B_, 128>>>(captions, emb, xe_h);
    f2h<<<(H_ * E_ / 4 + 255) / 256, 256>>>(fc1_w, fc1w_h, H_ * E_);
    f2h<<<(H_ * K_ / 4 + 255) / 256, 256>>>(att_wk, wk_h, H_ * K_);
    f2h<<<(B_ * S_ * K_ / 4 + 255) / 256, 256>>>(features, feat_h, B_ * S_ * K_);
    f2h<<<(V_ * H_ / 4 + 255) / 256, 256>>>(fc2_w, fc2w_h, V_ * H_);
    conv_wih_part<<<1536, 128>>>(gru_wih, wihx_h, 0);
    conv_wih_part<<<1536, 128>>>(gru_wih, wihc_h, 512);
    f2h<<<(512 * 512 / 4 + 255) / 256, 256>>>(att_wq, wcat_h, 512 * 512);
    f2h<<<(1536 * 512 / 4 + 255) / 256, 256>>>(gru_whh, wcat_h + 512 * 512,
                                               1536 * 512);
    transpose512<<<dim3(16, 16), dim3(32, 8)>>>(fc0_w, fc0wT);
    f2h<<<(512 * 512 / 4 + 255) / 256, 256>>>(fc0wT, fc0wT_h, 512 * 512);
    bias2_kernel<<<12, 128>>>(gru_wih, fc0_b, gru_bih, bias2);
    bcat_kernel<<<8, 256>>>(gru_bhh, bcat);

    // ---- prologue GEMMs (HMMA) ----
    // fc1: x_h = f16(xe @ fc1_w^T + b)            (1920 x 512 x 512)
    hgemm_nt<<<dim3(H_ / 128, TOUT * B_ / 128), 256>>>(
        xe_h, E_, fc1w_h, E_, x_h, H_, E_, fc1_b, 4);
    // keys = f16(features @ att_wk^T)             (25088 x 512 x 512)
    hgemm_nt<<<dim3(H_ / 128, B_ * S_ / 128), 256>>>(
        feat_h, K_, wk_h, K_, keys_h, H_, K_, nullptr, 5);
    // gix = x @ Wih_x^T (f32)                     (1920 x 1536 x 512)
    hgemm_nt<<<dim3(3 * H_ / 128, TOUT * B_ / 128), 256>>>(
        x_h, H_, wihx_h, H_, gix, 3 * H_, H_, nullptr, 0);
    // W' = f16(Wih_ctx @ fc0_w)                   (1536 x 512 x 512)
    hgemm_nt<<<dim3(4, 12), 256>>>(
        wihc_h, 512, fc0wT_h, 512, wprime_h, 512, 512, nullptr, 5);

    zero_kernel<<<(B_ * H_ + 1023) / 1024, 1024>>>(h, B_ * H_);
    zero_kernel<<<(B_ * H_ / 2 + 1023) / 1024, 1024>>>((float*)h16, B_ * H_ / 2);

    // ---- recurrence ----
    for (int t = 0; t < TOUT; ++t) {
        const __half* h16prev = h16 + (size_t)t * B_ * H_;
        float*        hprev   = h   + (size_t)t * B_ * H_;
        float*        hnew    = h   + (size_t)(t + 1) * B_ * H_;
        __half*       h16new  = h16 + (size_t)(t + 1) * B_ * H_;

        // [q | gh] = h @ [Wq ; Whh]^T + [0 ; bhh]   (128 x 2048 x 512)
        hgemm_s<<<2048 / 64, 256>>>(
            h16prev, wcat_h, 512, qgh, 2048, bcat, nullptr, 0, 1);

        attention_kernel<<<B_, 256>>>(qgh, keys_h, att_v, feat_h, ctx_h);

        // gi = ctx @ W'^T + bias2 + gix_t           (128 x 1536 x 512)
        hgemm_s<<<1536 / 64, 256>>>(
            ctx_h, wprime_h, 512, gi, 1536,
            bias2, gix + (size_t)t * B_ * 3 * H_, 1536, 2);

        gru_gate<<<B_ * H_ / 1024, 1024>>>(gi, qgh, hprev, hnew, h16new);
    }

    // ---- logits: HMMA (1920 x 32000 x 512), f32 out + bias + remap ----
    hgemm_nt<<<dim3(V_ / 128, TOUT * B_ / 128), 256>>>(
        h16 + B_ * H_, H_, fc2w_h, H_, out, V_, H_, fc2_b, 3);
}

// round 7
// speedup vs baseline: 7.4175x; 1.0645x over previous
#include <cuda_runtime.h>
#include <cuda_fp16.h>
#include <cuda_bf16.h>
#include <math.h>
#include <stdint.h>

// Problem dims
#define B_   128
#define S_   196
#define K_   512
#define TCAP 16
#define TOUT 15
#define V_   32000
#define E_   512
#define H_   512

// ---------------- scratch (device globals; allocation-free) ----------------
__device__ float g_gix[TOUT * B_ * 3 * H_];        // x_t @ Wx^T  (t*128+b, 1536)
__device__ float g_h[(TOUT + 1) * B_ * H_];        // h_0..h_15 fp32 master
__device__ float g_qgh[B_ * 2048];                 // per-step [q | gh]
__device__ float g_gi[B_ * 3 * H_];
__device__ float g_bcat[2048];                     // [0 ; gru_bhh]
__device__ float g_bias2[1536];                    // Wih_ctx@fc0_b + b_ih
__device__ float g_fc0wT[512 * 512];

// fp16 operands
__device__ __half g_xe_h[TOUT * B_ * E_];
__device__ __half g_x_h[TOUT * B_ * H_];
__device__ __half g_fc1w_h[H_ * E_];
__device__ __half g_wk_h[H_ * K_];
__device__ __half g_feat_h[(size_t)B_ * S_ * K_];
__device__ __half g_keys_h[(size_t)B_ * S_ * H_];
__device__ __half g_wihx_h[1536 * 512];
__device__ __half g_wihc_h[1536 * 512];
__device__ __half g_fc0wT_h[512 * 512];
__device__ __half g_fc2w_h[(size_t)V_ * H_];
__device__ __half g_h16[(TOUT + 1) * B_ * H_];     // fp16 h, slot 0 = zeros
__device__ __half g_ctx_h[B_ * K_];
__device__ __half g_wcat_h[2048 * 512];            // [att_wq ; gru_whh] fp16
__device__ __half g_wprime_h[1536 * 512];

// ---------------- fast math helpers ----------------------------------------
__device__ __forceinline__ float tanh_fast(float x) {
    float y;
    asm("tanh.approx.f32 %0, %1;" : "=f"(y) : "f"(x));
    return y;
}

// ========================= mma helpers =====================================
__device__ __forceinline__ void ldsm4(uint32_t* r, uint32_t addr) {
    asm volatile("ldmatrix.sync.aligned.m8n8.x4.shared.b16 {%0,%1,%2,%3}, [%4];"
        : "=r"(r[0]), "=r"(r[1]), "=r"(r[2]), "=r"(r[3]) : "r"(addr));
}
__device__ __forceinline__ void mma16816(float* c, const uint32_t* a, const uint32_t* b) {
    asm volatile("mma.sync.aligned.m16n8k16.row.col.f32.f16.f16.f32 "
        "{%0,%1,%2,%3}, {%4,%5,%6,%7}, {%8,%9}, {%0,%1,%2,%3};"
        : "+f"(c[0]), "+f"(c[1]), "+f"(c[2]), "+f"(c[3])
        : "r"(a[0]), "r"(a[1]), "r"(a[2]), "r"(a[3]), "r"(b[0]), "r"(b[1]));
}
__device__ __forceinline__ void cpasync16(uint32_t dst, const void* src) {
    asm volatile("cp.async.cg.shared.global [%0], [%1], 16;" :: "r"(dst), "l"(src));
}

// ============ fp16 HMMA NT GEMM, 3-stage cp.async pipeline =================
// C[M,N] = A[M,K]h * B[N,K]h^T ; BM=BN=128, BK=64, 256 thr, 8 warps (2m x 4n)
// Dynamic smem: 3 stages x (A 16KB + B 16KB) = 96KB. XOR-swizzled 128B rows.
// modes: 0 plain f32, 3 +bias remap (m=t*128+b -> row b*15+t),
//        4 +bias store fp16, 5 plain store fp16
#define HG_SMEM (3 * 32768)

__global__ __launch_bounds__(256) void hgemm_nt(
    const __half* __restrict__ A, int lda,
    const __half* __restrict__ B, int ldb,
    void* __restrict__ Cv, int ldc, int K,
    const float* __restrict__ bias, int mode)
{
    extern __shared__ __half sm[];
    uint32_t sb = (uint32_t)__cvta_generic_to_shared(sm);
    const int tid = threadIdx.x, lane = tid & 31, warp = tid >> 5;
    const int wm = warp & 1, wn = warp >> 1;
    const int bn = blockIdx.x, bm = blockIdx.y;

    const __half* Abase = A + (size_t)(bm * 128) * lda;
    const __half* Bbase = B + (size_t)(bn * 128) * ldb;

    // per-thread load geometry: 1024 16B chunks per operand per tile, 4/thread
    const int lrow = tid >> 1;            // wrong granularity? no: cid below
    (void)lrow;

    auto load_tile = [&](int kt, int st) {
        uint32_t abase_s = sb + st * 32768;
        uint32_t bbase_s = abase_s + 16384;
#pragma unroll
        for (int i = 0; i < 4; ++i) {
            int cid = i * 256 + tid;          // 0..1023
            int row = cid >> 3, c8 = cid & 7; // row 0..127, 16B chunk 0..7
            uint32_t soff = row * 128 + ((c8 * 16) ^ ((row & 7) * 16));
            cpasync16(abase_s + soff, Abase + (size_t)row * lda + kt * 64 + c8 * 8);
            cpasync16(bbase_s + soff, Bbase + (size_t)row * ldb + kt * 64 + c8 * 8);
        }
        asm volatile("cp.async.commit_group;" ::: "memory");
    };

    float acc[4][4][4] = {};
    const int a_r = ((lane >> 3) & 1) * 8 + (lane & 7);
    const int a_c = (lane >> 4) * 8;          // halves
    const int b_r = ((lane >> 4) & 1) * 8 + (lane & 7);
    const int b_c = ((lane >> 3) & 1) * 8;

    const int nkt = K / 64;
    load_tile(0, 0);
    if (nkt > 1) load_tile(1, 1);

    for (int kt = 0; kt < nkt; ++kt) {
        int st = kt % 3;
        if (kt + 1 < nkt) {
            asm volatile("cp.async.wait_group 1;" ::: "memory");
        } else {
            asm volatile("cp.async.wait_group 0;" ::: "memory");
        }
        __syncthreads();
        if (kt + 2 < nkt) load_tile(kt + 2, (kt + 2) % 3);

        uint32_t abase_s = sb + st * 32768;
        uint32_t bbase_s = abase_s + 16384;
#pragma unroll
        for (int ks = 0; ks < 4; ++ks) {
            int k = ks * 16;   // halves
            uint32_t af[4][4], bf[4][2];
#pragma unroll
            for (int mi = 0; mi < 4; ++mi) {
                int row = wm * 64 + mi * 16 + a_r;
                uint32_t addr = abase_s + row * 128 +
                                (((k + a_c) * 2) ^ ((row & 7) * 16));
                ldsm4(af[mi], addr);
            }
#pragma unroll
            for (int nh = 0; nh < 2; ++nh) {
                int row = wn * 32 + nh * 16 + b_r;
                uint32_t addr = bbase_s + row * 128 +
                                (((k + b_c) * 2) ^ ((row & 7) * 16));
                uint32_t r[4];
                ldsm4(r, addr);
                bf[2 * nh + 0][0] = r[0]; bf[2 * nh + 0][1] = r[1];
                bf[2 * nh + 1][0] = r[2]; bf[2 * nh + 1][1] = r[3];
            }
#pragma unroll
            for (int mi = 0; mi < 4; ++mi)
#pragma unroll
                for (int ni = 0; ni < 4; ++ni)
                    mma16816(acc[mi][ni], af[mi], bf[ni]);
        }
    }

    const int mb = bm * 128 + wm * 64;
    const int nb = bn * 128 + wn * 32;
    const int qr = lane >> 2, qc = (lane & 3) * 2;
#pragma unroll
    for (int mi = 0; mi < 4; ++mi) {
#pragma unroll
        for (int ni = 0; ni < 4; ++ni) {
            int n = nb + ni * 8 + qc;
            float bv = 0.f, bv2 = 0.f;
            if (mode == 3 || mode == 4) { bv = bias[n]; bv2 = bias[n + 1]; }
            float* c4 = acc[mi][ni];
#pragma unroll
            for (int half_ = 0; half_ < 2; ++half_) {
                int m = mb + mi * 16 + qr + half_ * 8;
                float v0 = c4[half_ * 2 + 0] + bv;
                float v1 = c4[half_ * 2 + 1] + bv2;
                if (mode == 4 || mode == 5) {
                    __half* C = (__half*)Cv;
                    *(__half2*)&C[(size_t)m * ldc + n] =
                        __halves2half2(__float2half(v0), __float2half(v1));
                } else if (mode == 3) {
                    int b = m & 127, t = m >> 7;
                    float* C = (float*)Cv;
                    *(float2*)&C[((size_t)b * TOUT + t) * ldc + n] = make_float2(v0, v1);
                } else {
                    float* C = (float*)Cv;
                    *(float2*)&C[(size_t)m * ldc + n] = make_float2(v0, v1);
                }
            }
        }
    }
}

// ============== fp16 tensor GEMM for recurrence: M=128, BN=64, BK=32 =======
// mode: 1 +bias f32 out ; 2 +bias +Add f32 out
__global__ __launch_bounds__(256) void hgemm_s(
    const __half* __restrict__ A,
    const __half* __restrict__ B, int ldb,
    float* __restrict__ C, int ldc,
    const float* __restrict__ bias,
    const float* __restrict__ Add, int ldadd, int mode)
{
    __shared__ __half As[2][128][40];
    __shared__ __half Bs[2][64][40];
    int tid = threadIdx.x, lane = tid & 31, warp = tid >> 5;
    int wm = warp >> 1, wn = warp & 1;
    int bn = blockIdx.x;

    int ar = tid >> 1, ac = (tid & 1) * 16;
    int br = tid >> 2, bc = (tid & 3) * 8;
    const __half* Ap = A + (size_t)ar * 512 + ac;
    const __half* Bp = B + (size_t)(bn * 64 + br) * ldb + bc;

    float acc[2][4][4] = {};
    int a_r = ((lane >> 3) & 1) * 8 + (lane & 7);
    int a_c = (lane >> 4) * 8;
    int b_r = ((lane >> 4) & 1) * 8 + (lane & 7);
    int b_c = ((lane >> 3) & 1) * 8;

    uint4 av0 = *(const uint4*)(Ap);
    uint4 av1 = *(const uint4*)(Ap + 8);
    uint4 bv  = *(const uint4*)(Bp);
    *(uint4*)&As[0][ar][ac] = av0; *(uint4*)&As[0][ar][ac + 8] = av1;
    *(uint4*)&Bs[0][br][bc] = bv;
    __syncthreads();

    int cur = 0;
#pragma unroll 4
    for (int kt = 0; kt < 16; ++kt) {
        if (kt < 15) {
            av0 = *(const uint4*)(Ap + (kt + 1) * 32);
            av1 = *(const uint4*)(Ap + (kt + 1) * 32 + 8);
            bv  = *(const uint4*)(Bp + (kt + 1) * 32);
        }
        uint32_t asb = (uint32_t)__cvta_generic_to_shared(&As[cur][0][0]);
        uint32_t bsb = (uint32_t)__cvta_generic_to_shared(&Bs[cur][0][0]);
#pragma unroll
        for (int ks = 0; ks < 2; ++ks) {
            int k = ks * 16;
            uint32_t af[2][4], bf[4][2];
#pragma unroll
            for (int mi = 0; mi < 2; ++mi) {
                uint32_t addr = asb +
                    (uint32_t)(((wm * 32 + mi * 16 + a_r) * 40 + k + a_c) * 2);
                ldsm4(af[mi], addr);
            }
#pragma unroll
            for (int nh = 0; nh < 2; ++nh) {
                uint32_t r[4];
                uint32_t addr = bsb +
                    (uint32_t)(((wn * 32 + nh * 16 + b_r) * 40 + k + b_c) * 2);
                ldsm4(r, addr);
                bf[2 * nh + 0][0] = r[0]; bf[2 * nh + 0][1] = r[1];
                bf[2 * nh + 1][0] = r[2]; bf[2 * nh + 1][1] = r[3];
            }
#pragma unroll
            for (int mi = 0; mi < 2; ++mi)
#pragma unroll
                for (int ni = 0; ni < 4; ++ni)
                    mma16816(acc[mi][ni], af[mi], bf[ni]);
        }
        if (kt < 15) {
            __syncthreads();
            cur ^= 1;
            *(uint4*)&As[cur][ar][ac] = av0; *(uint4*)&As[cur][ar][ac + 8] = av1;
            *(uint4*)&Bs[cur][br][bc] = bv;
            __syncthreads();
        }
    }

    int mb = wm * 32;
    int nb = bn * 64 + wn * 32;
    int qr = lane >> 2, qc = (lane & 3) * 2;
#pragma unroll
    for (int mi = 0; mi < 2; ++mi) {
#pragma unroll
        for (int ni = 0; ni < 4; ++ni) {
            int n = nb + ni * 8 + qc;
            float bv0 = bias[n], bv1 = bias[n + 1];
            float* c4 = acc[mi][ni];
#pragma unroll
            for (int half_ = 0; half_ < 2; ++half_) {
                int m = mb + mi * 16 + qr + half_ * 8;
                float v0 = c4[half_ * 2 + 0] + bv0;
                float v1 = c4[half_ * 2 + 1] + bv1;
                if (mode == 2) {
                    v0 += Add[(size_t)m * ldadd + n];
                    v1 += Add[(size_t)m * ldadd + n + 1];
                }
                *(float2*)&C[(size_t)m * ldc + n] = make_float2(v0, v1);
            }
        }
    }
}

// -------- embedding gather -> fp16 -----------------------------------------
__global__ void gather_embed_h(const int* __restrict__ captions,
                               const float* __restrict__ emb,
                               __half* __restrict__ xe)
{
    int m = blockIdx.x;            // m = t*128 + b
    int t = m >> 7, b = m & 127;
    int cap = captions[b * TCAP + t];
    float4 v = ((const float4*)(emb + (size_t)cap * E_))[threadIdx.x];
    __half2* dst = (__half2*)(xe + (size_t)m * E_);
    dst[2 * threadIdx.x + 0] = __floats2half2_rn(v.x, v.y);
    dst[2 * threadIdx.x + 1] = __floats2half2_rn(v.z, v.w);
}

// -------- generic f32 -> f16 (n % 4 == 0) -----------------------------------
__global__ void f2h(const float* __restrict__ in, __half* __restrict__ out, int n)
{
    int i = (blockIdx.x * blockDim.x + threadIdx.x) * 4;
    if (i < n) {
        float4 v = *(const float4*)(in + i);
        ((__half2*)(out + i))[0] = __floats2half2_rn(v.x, v.y);
        ((__half2*)(out + i))[1] = __floats2half2_rn(v.z, v.w);
    }
}

// -------- gru_wih column-slice -> fp16 compact (offset 0 or 512) ------------
__global__ void conv_wih_part(const float* __restrict__ wih, __half* __restrict__ out,
                              int off)
{
    int n = blockIdx.x;            // 0..1535
    int t = threadIdx.x;           // 0..127
    float4 v = *(const float4*)(wih + (size_t)n * 1024 + off + t * 4);
    __half2* o = (__half2*)(out + (size_t)n * 512 + t * 4);
    o[0] = __floats2half2_rn(v.x, v.y);
    o[1] = __floats2half2_rn(v.z, v.w);
}

// -------- 512x512 transpose --------------------------------------------------
__global__ void transpose512(const float* __restrict__ in, float* __restrict__ out)
{
    __shared__ float tile[32][33];
    int x = blockIdx.x * 32 + threadIdx.x;
    int y = blockIdx.y * 32 + threadIdx.y;
#pragma unroll
    for (int j = 0; j < 4; ++j)
        tile[threadIdx.y + 8 * j][threadIdx.x] = in[(size_t)(y + 8 * j) * 512 + x];
    __syncthreads();
    int x2 = blockIdx.y * 32 + threadIdx.x;
    int y2 = blockIdx.x * 32 + threadIdx.y;
#pragma unroll
    for (int j = 0; j < 4; ++j)
        out[(size_t)(y2 + 8 * j) * 512 + x2] = tile[threadIdx.x][threadIdx.y + 8 * j];
}

// -------- bias2 = Wih_ctx @ fc0_b + b_ih ------------------------------------
__global__ void bias2_kernel(const float* __restrict__ wih, const float* __restrict__ fc0b,
                             const float* __restrict__ bih, float* __restrict__ out)
{
    int n = blockIdx.x * blockDim.x + threadIdx.x;
    if (n < 1536) {
        float s = 0.f;
        for (int j = 0; j < 512; ++j) s += wih[(size_t)n * 1024 + 512 + j] * fc0b[j];
        out[n] = s + bih[n];
    }
}

__global__ void bcat_kernel(const float* __restrict__ bhh, float* __restrict__ out)
{
    int j = blockIdx.x * blockDim.x + threadIdx.x;
    if (j < 2048) out[j] = (j < 512) ? 0.f : bhh[j - 512];
}

// -------- fused Bahdanau attention (fp16 keys/features, fp16 ctx out) -------
__global__ __launch_bounds__(256) void attention_kernel(
    const float* __restrict__ qgh,       // (B, 2048): q is cols [0,512)
    const __half* __restrict__ keys,     // (B,S,H) fp16
    const float* __restrict__ att_v,     // (H)
    const __half* __restrict__ features, // (B,S,K) fp16
    __half* __restrict__ ctx)            // (B,K) fp16
{
    __shared__ float qs[H_];
    __shared__ float av[H_];
    __shared__ float sc[S_];
    __shared__ float red[8];

    int b = blockIdx.x, tid = threadIdx.x;
    for (int i = tid; i < H_; i += 256) { qs[i] = qgh[b * 2048 + i]; av[i] = att_v[i]; }
    __syncthreads();

    int warp = tid >> 5, lane = tid & 31;
    const __half2* kpb = (const __half2*)(keys + (size_t)b * S_ * H_);
    for (int s = warp; s < S_; s += 8) {
        const __half2* kps = kpb + (size_t)s * (H_ / 2);
        float acc = 0.f;
        for (int i = lane; i < H_ / 2; i += 32) {
            float2 kv = __half22float2(kps[i]);
            acc += av[2 * i]     * tanh_fast(qs[2 * i]     + kv.x)
                 + av[2 * i + 1] * tanh_fast(qs[2 * i + 1] + kv.y);
        }
#pragma unroll
        for (int o = 16; o; o >>= 1) acc += __shfl_xor_sync(~0u, acc, o);
        if (!lane) sc[s] = acc;
    }
    __syncthreads();

    float m = -INFINITY;
    for (int s = tid; s < S_; s += 256) m = fmaxf(m, sc[s]);
#pragma unroll
    for (int o = 16; o; o >>= 1) m = fmaxf(m, __shfl_xor_sync(~0u, m, o));
    if (!lane) red[warp] = m;
    __syncthreads();
    m = red[0];
#pragma unroll
    for (int w = 1; w < 8; ++w) m = fmaxf(m, red[w]);
    __syncthreads();

    float ls = 0.f;
    for (int s = tid; s < S_; s += 256) { float e = __expf(sc[s] - m); sc[s] = e; ls += e; }
#pragma unroll
    for (int o = 16; o; o >>= 1) ls += __shfl_xor_sync(~0u, ls, o);
    if (!lane) red[warp] = ls;
    __syncthreads();
    float sum = 0.f;
#pragma unroll
    for (int w = 0; w < 8; ++w) sum += red[w];
    float inv = 1.f / sum;

    const __half* fb = features + (size_t)b * S_ * K_;
    for (int k = tid; k < K_; k += 256) {
        float acc = 0.f;
        for (int s = 0; s < S_; ++s)
            acc += sc[s] * __half2float(fb[(size_t)s * K_ + k]);
        ctx[b * K_ + k] = __float2half(acc * inv);
    }
}

// -------- GRU gates (writes fp32 master + fp16 copy) ------------------------
__global__ void gru_gate(const float* __restrict__ gi, const float* __restrict__ qgh,
                         const float* __restrict__ hprev, float* __restrict__ hnew,
                         __half* __restrict__ hnew16)
{
    int idx = blockIdx.x * blockDim.x + threadIdx.x;   // 0..65535
    int b = idx >> 9, j = idx & 511;
    const float* ghb = qgh + (size_t)b * 2048 + 512;
    int base = b * 1536 + j;
    float ir = gi[base], iz = gi[base + 512], in_ = gi[base + 1024];
    float hr = ghb[j], hz = ghb[512 + j], hn = ghb[1024 + j];
    float r = 1.f / (1.f + __expf(-(ir + hr)));
    float z = 1.f / (1.f + __expf(-(iz + hz)));
    float n = tanh_fast(in_ + r * hn);
    float v = (1.f - z) * n + z * hprev[idx];
    hnew[idx] = v;
    hnew16[idx] = __float2half(v);
}

__global__ void zero_kernel(float* p, int n)
{
    int idx = blockIdx.x * blockDim.x + threadIdx.x;
    if (idx < n) p[idx] = 0.f;
}

// ---------------- launch -----------------------------------------------------
extern "C" void kernel_launch(void* const* d_in, const int* in_sizes, int n_in,
                              void* d_out, int out_size)
{
    const float* features = (const float*)d_in[0];
    const int*   captions = (const int*)  d_in[1];
    const float* emb      = (const float*)d_in[2];
    const float* fc1_w    = (const float*)d_in[3];
    const float* fc1_b    = (const float*)d_in[4];
    const float* att_wq   = (const float*)d_in[5];
    const float* att_wk   = (const float*)d_in[6];
    const float* att_v    = (const float*)d_in[7];
    const float* fc0_w    = (const float*)d_in[8];
    const float* fc0_b    = (const float*)d_in[9];
    const float* gru_wih  = (const float*)d_in[10];
    const float* gru_whh  = (const float*)d_in[11];
    const float* gru_bih  = (const float*)d_in[12];
    const float* gru_bhh  = (const float*)d_in[13];
    const float* fc2_w    = (const float*)d_in[14];
    const float* fc2_b    = (const float*)d_in[15];
    float* out = (float*)d_out;

    float *gix, *h, *qgh, *gi, *bcat, *bias2, *fc0wT;
    __half *xe_h, *x_h, *fc1w_h, *wk_h, *feat_h, *keys_h, *wihx_h, *wihc_h;
    __half *fc0wT_h, *fc2w_h, *h16, *ctx_h, *wcat_h, *wprime_h;
    cudaGetSymbolAddress((void**)&gix,      g_gix);
    cudaGetSymbolAddress((void**)&h,        g_h);
    cudaGetSymbolAddress((void**)&qgh,      g_qgh);
    cudaGetSymbolAddress((void**)&gi,       g_gi);
    cudaGetSymbolAddress((void**)&bcat,     g_bcat);
    cudaGetSymbolAddress((void**)&bias2,    g_bias2);
    cudaGetSymbolAddress((void**)&fc0wT,    g_fc0wT);
    cudaGetSymbolAddress((void**)&xe_h,     g_xe_h);
    cudaGetSymbolAddress((void**)&x_h,      g_x_h);
    cudaGetSymbolAddress((void**)&fc1w_h,   g_fc1w_h);
    cudaGetSymbolAddress((void**)&wk_h,     g_wk_h);
    cudaGetSymbolAddress((void**)&feat_h,   g_feat_h);
    cudaGetSymbolAddress((void**)&keys_h,   g_keys_h);
    cudaGetSymbolAddress((void**)&wihx_h,   g_wihx_h);
    cudaGetSymbolAddress((void**)&wihc_h,   g_wihc_h);
    cudaGetSymbolAddress((void**)&fc0wT_h,  g_fc0wT_h);
    cudaGetSymbolAddress((void**)&fc2w_h,   g_fc2w_h);
    cudaGetSymbolAddress((void**)&h16,      g_h16);
    cudaGetSymbolAddress((void**)&ctx_h,    g_ctx_h);
    cudaGetSymbolAddress((void**)&wcat_h,   g_wcat_h);
    cudaGetSymbolAddress((void**)&wprime_h, g_wprime_h);

    cudaFuncSetAttribute(hgemm_nt, cudaFuncAttributeMaxDynamicSharedMemorySize,
                         HG_SMEM);

    // ---- conversions ----
    gather_embed_h<<<TOUT * B_, 128>>>(captions, emb, xe_h);
    f2h<<<(H_ * E_ / 4 + 255) / 256, 256>>>(fc1_w, fc1w_h, H_ * E_);
    f2h<<<(H_ * K_ / 4 + 255) / 256, 256>>>(att_wk, wk_h, H_ * K_);
    f2h<<<(B_ * S_ * K_ / 4 + 255) / 256, 256>>>(features, feat_h, B_ * S_ * K_);
    f2h<<<(V_ * H_ / 4 + 255) / 256, 256>>>(fc2_w, fc2w_h, V_ * H_);
    conv_wih_part<<<1536, 128>>>(gru_wih, wihx_h, 0);
    conv_wih_part<<<1536, 128>>>(gru_wih, wihc_h, 512);
    f2h<<<(512 * 512 / 4 + 255) / 256, 256>>>(att_wq, wcat_h, 512 * 512);
    f2h<<<(1536 * 512 / 4 + 255) / 256, 256>>>(gru_whh, wcat_h + 512 * 512,
                                               1536 * 512);
    transpose512<<<dim3(16, 16), dim3(32, 8)>>>(fc0_w, fc0wT);
    f2h<<<(512 * 512 / 4 + 255) / 256, 256>>>(fc0wT, fc0wT_h, 512 * 512);
    bias2_kernel<<<12, 128>>>(gru_wih, fc0_b, gru_bih, bias2);
    bcat_kernel<<<8, 256>>>(gru_bhh, bcat);

    // ---- prologue GEMMs (pipelined HMMA) ----
    // fc1: x_h = f16(xe @ fc1_w^T + b)            (1920 x 512 x 512)
    hgemm_nt<<<dim3(H_ / 128, TOUT * B_ / 128), 256, HG_SMEM>>>(
        xe_h, E_, fc1w_h, E_, x_h, H_, E_, fc1_b, 4);
    // keys = f16(features @ att_wk^T)             (25088 x 512 x 512)
    hgemm_nt<<<dim3(H_ / 128, B_ * S_ / 128), 256, HG_SMEM>>>(
        feat_h, K_, wk_h, K_, keys_h, H_, K_, nullptr, 5);
    // gix = x @ Wih_x^T (f32)                     (1920 x 1536 x 512)
    hgemm_nt<<<dim3(3 * H_ / 128, TOUT * B_ / 128), 256, HG_SMEM>>>(
        x_h, H_, wihx_h, H_, gix, 3 * H_, H_, nullptr, 0);
    // W' = f16(Wih_ctx @ fc0_w)                   (1536 x 512 x 512)
    hgemm_nt<<<dim3(4, 12), 256, HG_SMEM>>>(
        wihc_h, 512, fc0wT_h, 512, wprime_h, 512, 512, nullptr, 5);

    zero_kernel<<<(B_ * H_ + 1023) / 1024, 1024>>>(h, B_ * H_);
    zero_kernel<<<(B_ * H_ / 2 + 1023) / 1024, 1024>>>((float*)h16, B_ * H_ / 2);

    // ---- recurrence ----
    for (int t = 0; t < TOUT; ++t) {
        const __half* h16prev = h16 + (size_t)t * B_ * H_;
        float*        hprev   = h   + (size_t)t * B_ * H_;
        float*        hnew    = h   + (size_t)(t + 1) * B_ * H_;
        __half*       h16new  = h16 + (size_t)(t + 1) * B_ * H_;

        // [q | gh] = h @ [Wq ; Whh]^T + [0 ; bhh]   (128 x 2048 x 512)
        hgemm_s<<<2048 / 64, 256>>>(
            h16prev, wcat_h, 512, qgh, 2048, bcat, nullptr, 0, 1);

        attention_kernel<<<B_, 256>>>(qgh, keys_h, att_v, feat_h, ctx_h);

        // gi = ctx @ W'^T + bias2 + gix_t           (128 x 1536 x 512)
        hgemm_s<<<1536 / 64, 256>>>(
            ctx_h, wprime_h, 512, gi, 1536,
            bias2, gix + (size_t)t * B_ * 3 * H_, 1536, 2);

        gru_gate<<<B_ * H_ / 1024, 1024>>>(gi, qgh, hprev, hnew, h16new);
    }

    // ---- logits: pipelined HMMA (1920 x 32000 x 512), f32 + bias + remap ----
    hgemm_nt<<<dim3(V_ / 128, TOUT * B_ / 128), 256, HG_SMEM>>>(
        h16 + B_ * H_, H_, fc2w_h, H_, out, V_, H_, fc2_b, 3);
}